// round 14
// baseline (speedup 1.0000x reference)
#include <cuda_runtime.h>
#include <cuda_fp16.h>
#include <cstdint>

// Problem constants
#define B_   32
#define CIN  1024
#define COUT 512
#define NSP  1568          // T*H*W = 8*14*14
#define NHEAD 8
#define DK   64
#define NCHUNK 7
#define CHUNK 224          // 1568 / 7

// Scratch buffers (device globals: allocation-free contract)
__device__ __half g_kh[(size_t)B_ * COUT * NSP];
__device__ __half g_qph[(size_t)B_ * COUT * NSP];
__device__ __half g_vh[(size_t)B_ * COUT * NSP];
__device__ __half g_oh[(size_t)B_ * COUT * NSP];
__device__ __half g_xh[(size_t)B_ * CIN * NSP];
__device__ __half g_qh[(size_t)B_ * CIN * NSP];
__device__ __half g_wh[4 * 512 * 1024];          // key_w, query_w, val_w, up_w
__device__ float  g_spart[(size_t)B_ * NHEAD * NCHUNK * DK * DK];
__device__ float  g_p[(size_t)B_ * NHEAD * DK * DK];

// ---------------------------------------------------------------------------
// PTX helpers
// ---------------------------------------------------------------------------
__device__ __forceinline__ uint32_t smem_u32(const void* p) {
    uint32_t a;
    asm("{ .reg .u64 t; cvta.to.shared.u64 t, %1; cvt.u32.u64 %0, t; }"
        : "=r"(a) : "l"(p));
    return a;
}

__device__ __forceinline__ void cp16(uint32_t dst, const void* src, uint32_t srcsize) {
    asm volatile("cp.async.cg.shared.global [%0], [%1], 16, %2;"
                 :: "r"(dst), "l"(src), "r"(srcsize) : "memory");
}
#define CP_COMMIT() asm volatile("cp.async.commit_group;" ::: "memory")
#define CP_WAIT1()  asm volatile("cp.async.wait_group 1;" ::: "memory")

__device__ __forceinline__ void ldsm4(uint32_t* r, uint32_t addr) {
    asm volatile("ldmatrix.sync.aligned.m8n8.x4.shared.b16 {%0,%1,%2,%3}, [%4];"
                 : "=r"(r[0]), "=r"(r[1]), "=r"(r[2]), "=r"(r[3]) : "r"(addr));
}
__device__ __forceinline__ void ldsm4t(uint32_t* r, uint32_t addr) {
    asm volatile("ldmatrix.sync.aligned.m8n8.x4.trans.shared.b16 {%0,%1,%2,%3}, [%4];"
                 : "=r"(r[0]), "=r"(r[1]), "=r"(r[2]), "=r"(r[3]) : "r"(addr));
}

__device__ __forceinline__ void mma16(float* d, const uint32_t* a, const uint32_t* b) {
    asm volatile(
        "mma.sync.aligned.m16n8k16.row.col.f32.f16.f16.f32 "
        "{%0,%1,%2,%3},{%4,%5,%6,%7},{%8,%9},{%0,%1,%2,%3};"
        : "+f"(d[0]), "+f"(d[1]), "+f"(d[2]), "+f"(d[3])
        : "r"(a[0]), "r"(a[1]), "r"(a[2]), "r"(a[3]), "r"(b[0]), "r"(b[1]));
}

// ---------------------------------------------------------------------------
// FP16 GEMM: Y[m,n] = sum_k A[m,k]*B[k,n] + bias[m]
// BM=BN=128, BK=64, 128 threads (4 warps 2m x 2n), warp tile 64x64.
// 3-stage cp.async pipeline; ldmatrix (A: 144B rows, B: 272B rows, both
// conflict-free). 2 CTAs/SM. Fragments double-buffered: ks+1 loads overlap
// ks MMAs. M%128==0, K%64==0.
// ---------------------------------------------------------------------------
#define A_ROWB   144
#define B_ROWB   272
#define A_BYTES  (128 * A_ROWB)            // 18432
#define B_BYTES  (64 * B_ROWB)             // 17408
#define STAGE_B  (A_BYTES + B_BYTES)       // 35840
#define GEMM_SMEM_BYTES (3 * STAGE_B)      // 107520
#define GTHREADS 128

__device__ __forceinline__ void gemm_issue(
    const __half* __restrict__ A, const __half* __restrict__ B,
    int K, int N, int m0, int n0, int kt, uint32_t sbase, int tid)
{
    const uint32_t st = sbase + (kt % 3) * STAGE_B;
#pragma unroll
    for (int i = 0; i < 8; i++) {
        const int id = tid + GTHREADS * i;
        const int r = id >> 3, c = id & 7;
        cp16(st + r * A_ROWB + c * 16,
             A + (size_t)(m0 + r) * K + kt * 64 + c * 8, 16);
    }
#pragma unroll
    for (int i = 0; i < 8; i++) {
        const int id = tid + GTHREADS * i;
        const int k = id >> 4, c = id & 15;
        const int n = n0 + c * 8;
        cp16(st + A_BYTES + k * B_ROWB + c * 16,
             B + (size_t)(kt * 64 + k) * N + n, (n < N) ? 16u : 0u);
    }
}

__device__ __forceinline__ void load_frags(
    uint32_t st, uint32_t a_addr, uint32_t b_addr, int ks,
    uint32_t af[4][4], uint32_t bf[8][2])
{
#pragma unroll
    for (int mt = 0; mt < 4; mt++)
        ldsm4(af[mt], st + a_addr + mt * 16 * A_ROWB + ks * 32);
#pragma unroll
    for (int p = 0; p < 4; p++) {
        uint32_t t[4];
        ldsm4t(t, st + b_addr + ks * 16 * B_ROWB + p * 32);
        bf[2 * p][0] = t[0]; bf[2 * p][1] = t[1];
        bf[2 * p + 1][0] = t[2]; bf[2 * p + 1][1] = t[3];
    }
}

template <bool HALF_OUT, typename OutT>
__device__ __forceinline__ void gemm_body(
    const __half* __restrict__ A, const __half* __restrict__ B,
    const float* __restrict__ bias, OutT* __restrict__ Y,
    int M, int N, int K, int m0, int n0, uint8_t* smem)
{
    const int tid  = threadIdx.x;
    const int lane = tid & 31;
    const int w    = tid >> 5;          // 0..3
    const int g    = lane >> 2;
    const int c    = lane & 3;
    const int wm   = (w & 1) << 6;      // 0/64
    const int wn   = (w >> 1) << 6;     // 0/64

    const uint32_t sbase = smem_u32(smem);
    const int KT = K >> 6;

    float acc[4][8][4];
#pragma unroll
    for (int mt = 0; mt < 4; mt++)
#pragma unroll
        for (int nt = 0; nt < 8; nt++)
#pragma unroll
            for (int r = 0; r < 4; r++) acc[mt][nt][r] = 0.f;

    const uint32_t a_addr = (uint32_t)((wm + (lane & 15)) * A_ROWB + (lane >> 4) * 16);
    const uint32_t b_addr = (uint32_t)(A_BYTES + (lane & 15) * B_ROWB
                                       + (wn + (lane >> 4) * 8) * 2);

    // prologue: 2 stages in flight
    gemm_issue(A, B, K, N, m0, n0, 0, sbase, tid); CP_COMMIT();
    if (KT > 1) gemm_issue(A, B, K, N, m0, n0, 1, sbase, tid);
    CP_COMMIT();

    uint32_t af[2][4][4];
    uint32_t bf[2][8][2];

    for (int kt = 0; kt < KT; kt++) {
        CP_WAIT1();                 // stage kt resident
        __syncthreads();
        if (kt + 2 < KT) gemm_issue(A, B, K, N, m0, n0, kt + 2, sbase, tid);
        CP_COMMIT();

        const uint32_t st = sbase + (kt % 3) * STAGE_B;
        load_frags(st, a_addr, b_addr, 0, af[0], bf[0]);
#pragma unroll
        for (int ks = 0; ks < 4; ks++) {
            const int cur = ks & 1;
            if (ks < 3)
                load_frags(st, a_addr, b_addr, ks + 1, af[cur ^ 1], bf[cur ^ 1]);
#pragma unroll
            for (int mt = 0; mt < 4; mt++)
#pragma unroll
                for (int nt = 0; nt < 8; nt++)
                    mma16(acc[mt][nt], af[cur][mt], bf[cur][nt]);
        }
    }

    // ---- epilogue: bias + guarded stores ----
#pragma unroll
    for (int mt = 0; mt < 4; mt++) {
        const int mrow = m0 + wm + mt * 16 + g;
        const float bb0 = bias[mrow];
        const float bb1 = bias[mrow + 8];
#pragma unroll
        for (int nt = 0; nt < 8; nt++) {
            const int n = n0 + wn + nt * 8 + 2 * c;
            if (n < N) {
                if (HALF_OUT) {
                    __half2 h0 = __floats2half2_rn(acc[mt][nt][0] + bb0,
                                                   acc[mt][nt][1] + bb0);
                    __half2 h1 = __floats2half2_rn(acc[mt][nt][2] + bb1,
                                                   acc[mt][nt][3] + bb1);
                    *(__half2*)((__half*)Y + (size_t)mrow * N + n)       = h0;
                    *(__half2*)((__half*)Y + (size_t)(mrow + 8) * N + n) = h1;
                } else {
                    float2 o0, o1;
                    o0.x = acc[mt][nt][0] + bb0; o0.y = acc[mt][nt][1] + bb0;
                    o1.x = acc[mt][nt][2] + bb1; o1.y = acc[mt][nt][3] + bb1;
                    *(float2*)((float*)Y + (size_t)mrow * N + n)       = o0;
                    *(float2*)((float*)Y + (size_t)(mrow + 8) * N + n) = o1;
                }
            }
        }
    }
}

// ---------------------------------------------------------------------------
// Fused conversion kernel: inputs (x, query) + 4 weight matrices
// ---------------------------------------------------------------------------
__global__ void __launch_bounds__(256)
convert_all_kernel(const float* __restrict__ x, const float* __restrict__ q,
                   __half* __restrict__ xh, __half* __restrict__ qh,
                   const float* __restrict__ w0, const float* __restrict__ w1,
                   const float* __restrict__ w2, const float* __restrict__ w3,
                   __half* __restrict__ wdst)
{
    const size_t n4in = (size_t)B_ * CIN * NSP / 4;       // float4s per input
    const int    seg  = 512 * 1024 / 4;                   // float4s per weight
    const size_t total = 2 * n4in + 4 * (size_t)seg;
    const size_t stride = (size_t)gridDim.x * blockDim.x;
    for (size_t i = (size_t)blockIdx.x * blockDim.x + threadIdx.x; i < total; i += stride) {
        const float* src; __half* dst; size_t j;
        if (i < n4in)            { src = x; dst = xh; j = i; }
        else if (i < 2 * n4in)   { src = q; dst = qh; j = i - n4in; }
        else {
            size_t wi = i - 2 * n4in;
            const int which = (int)(wi / seg);
            j = wi % seg;
            src = (which == 0) ? w0 : (which == 1) ? w1 : (which == 2) ? w2 : w3;
            dst = wdst + (size_t)which * 512 * 1024;
        }
        float4 v = ((const float4*)src)[j];
        ((__half2*)dst)[2 * j]     = __floats2half2_rn(v.x, v.y);
        ((__half2*)dst)[2 * j + 1] = __floats2half2_rn(v.z, v.w);
    }
}

// ---------------------------------------------------------------------------
// GEMM launch wrappers
// ---------------------------------------------------------------------------
struct ProjArgs {
    const __half* X[3];
    __half*       Y[3];
    const float*  bias[3];
};

__global__ void __launch_bounds__(GTHREADS, 2)
proj3_kernel(ProjArgs pa, const __half* __restrict__ Wh)
{
    extern __shared__ uint8_t smem[];
    const int which = blockIdx.z % 3;
    const int b     = blockIdx.z / 3;
    gemm_body<true>(Wh + (size_t)which * 512 * 1024,
                    pa.X[which] + (size_t)b * CIN * NSP,
                    pa.bias[which],
                    pa.Y[which] + (size_t)b * COUT * NSP,
                    COUT, NSP, CIN, blockIdx.y * 128, blockIdx.x * 128, smem);
}

__global__ void __launch_bounds__(GTHREADS, 2)
up_kernel(const __half* __restrict__ Wh, const __half* __restrict__ X,
          const float* __restrict__ bias, float* __restrict__ Y)
{
    extern __shared__ uint8_t smem[];
    const int b = blockIdx.z;
    gemm_body<false>(Wh + (size_t)3 * 512 * 1024,
                     X + (size_t)b * COUT * NSP, bias, Y + (size_t)b * CIN * NSP,
                     CIN, NSP, COUT, blockIdx.y * 128, blockIdx.x * 128, smem);
}

// ---------------------------------------------------------------------------
// Attention — unchanged from R13.
// ---------------------------------------------------------------------------
#define KST 72    // halves; 144B rows -> ldmatrix conflict-free

__global__ void __launch_bounds__(128)
attn_s_kernel(const __half* __restrict__ Kp, const __half* __restrict__ Qp,
              float* __restrict__ Sp)
{
    const int bh = blockIdx.x;
    const int ch = blockIdx.y;
    const int b = bh >> 3;
    const int h = bh & 7;
    const size_t base = (size_t)b * (COUT * NSP);
    const __half* Kb = Kp + base + h * DK;
    const __half* Qb = Qp + base + h * DK;

    __shared__ __half Ksm[32 * KST];
    __shared__ __half Qsm[32 * KST];
    const uint32_t ksb = smem_u32(Ksm);
    const uint32_t qsb = smem_u32(Qsm);

    const int tid  = threadIdx.x;
    const int lane = tid & 31;
    const int w    = tid >> 5;
    const int wm   = (w & 1) << 5;
    const int wn   = (w >> 1) << 5;

    float acc[2][4][4];
#pragma unroll
    for (int mt = 0; mt < 2; mt++)
#pragma unroll
        for (int nt = 0; nt < 4; nt++)
#pragma unroll
            for (int r = 0; r < 4; r++) acc[mt][nt][r] = 0.f;

    const int r  = tid >> 3;
    const int c8 = (tid & 7) << 3;

    const int n0 = ch * CHUNK;
    for (int nb = n0; nb < n0 + CHUNK; nb += 32) {
#pragma unroll
        for (int u = 0; u < 2; u++) {
            const int rr = r + u * 16;
            const size_t gg = (size_t)(nb + rr) * COUT + c8;
            *(uint4*)&Ksm[rr * KST + c8] = *(const uint4*)&Kb[gg];
            *(uint4*)&Qsm[rr * KST + c8] = *(const uint4*)&Qb[gg];
        }
        __syncthreads();

#pragma unroll
        for (int s = 0; s < 2; s++) {
            const uint32_t krow = (uint32_t)((s * 16 + (lane & 15)) * KST * 2);
            const uint32_t cblk = (uint32_t)((lane >> 4) * 8 * 2);
            uint32_t t[4];
            uint32_t af[2][4];
#pragma unroll
            for (int mt = 0; mt < 2; mt++) {
                ldsm4t(t, ksb + krow + (uint32_t)((wm + mt * 16) * 2) + cblk);
                af[mt][0] = t[0]; af[mt][1] = t[2];
                af[mt][2] = t[1]; af[mt][3] = t[3];
            }
            uint32_t bf[4][2];
#pragma unroll
            for (int p = 0; p < 2; p++) {
                ldsm4t(t, qsb + krow + (uint32_t)((wn + p * 16) * 2) + cblk);
                bf[2 * p][0] = t[0]; bf[2 * p][1] = t[1];
                bf[2 * p + 1][0] = t[2]; bf[2 * p + 1][1] = t[3];
            }
#pragma unroll
            for (int mt = 0; mt < 2; mt++)
#pragma unroll
                for (int nt = 0; nt < 4; nt++)
                    mma16(acc[mt][nt], af[mt], bf[nt]);
        }
        __syncthreads();
    }

    float* out = Sp + ((size_t)bh * NCHUNK + ch) * (DK * DK);
    const int g = lane >> 2, cc = lane & 3;
#pragma unroll
    for (int mt = 0; mt < 2; mt++) {
        const int i0 = wm + mt * 16 + g;
#pragma unroll
        for (int nt = 0; nt < 4; nt++) {
            const int j = wn + nt * 8 + 2 * cc;
            float2 d0, d1;
            d0.x = acc[mt][nt][0]; d0.y = acc[mt][nt][1];
            d1.x = acc[mt][nt][2]; d1.y = acc[mt][nt][3];
            *(float2*)&out[i0 * DK + j]       = d0;
            *(float2*)&out[(i0 + 8) * DK + j] = d1;
        }
    }
}

__global__ void __launch_bounds__(64)
attn_softmax_kernel(const float* __restrict__ Sp, float* __restrict__ P)
{
    const int bh = blockIdx.x;
    const int i  = threadIdx.x;

    const float* sp = Sp + (size_t)bh * NCHUNK * DK * DK + i * DK;
    float s[64];
#pragma unroll 16
    for (int j = 0; j < 64; j++) s[j] = sp[j];
    for (int c = 1; c < NCHUNK; c++) {
        const float* q = sp + c * DK * DK;
#pragma unroll 16
        for (int j = 0; j < 64; j++) s[j] += q[j];
    }
    float mx = -1e30f;
#pragma unroll 16
    for (int j = 0; j < 64; j++) { s[j] *= 0.125f; mx = fmaxf(mx, s[j]); }
    float sum = 0.f;
#pragma unroll 16
    for (int j = 0; j < 64; j++) { s[j] = expf(s[j] - mx); sum += s[j]; }
    const float inv = 1.0f / sum;
    float* out = P + (size_t)bh * DK * DK + i * DK;
#pragma unroll 16
    for (int j = 0; j < 64; j++) out[j] = s[j] * inv;
}

#define PST 68    // floats; 272B rows, float4-aligned
__global__ void __launch_bounds__(256)
attn_o_kernel(const float* __restrict__ P, const __half* __restrict__ Vp,
              __half* __restrict__ Op)
{
    const int bh = blockIdx.x;
    const int ch = blockIdx.y;
    const int b = bh >> 3;
    const int h = bh & 7;
    const size_t base = (size_t)b * (COUT * NSP);
    const __half* Vb = Vp + base + h * DK;
    __half*       Ob = Op + base;

    __shared__ float Ps[64 * PST];
    __shared__ float Vs[32 * PST];

    const int tid = threadIdx.x;
    const int tx = tid & 15;
    const int ty = tid >> 4;

    {
        const float* p = P + (size_t)bh * DK * DK;
#pragma unroll
        for (int u = 0; u < 4; u++) {
            const int idx = tid + u * 256;
            const int row = idx >> 4;
            const int c4  = (idx & 15) << 2;
            *(float4*)&Ps[row * PST + c4] = *(const float4*)&p[row * DK + c4];
        }
    }
    __syncthreads();

    const int r  = tid >> 3;
    const int c8 = (tid & 7) << 3;

    const int n0 = ch * CHUNK;
    for (int nb = n0; nb < n0 + CHUNK; nb += 32) {
        {
            uint4 u = *(const uint4*)&Vb[(size_t)(nb + r) * COUT + c8];
            const __half2* h2 = (const __half2*)&u;
#pragma unroll
            for (int q = 0; q < 4; q++) {
                float2 f = __half22float2(h2[q]);
                Vs[r * PST + c8 + 2 * q]     = f.x;
                Vs[r * PST + c8 + 2 * q + 1] = f.y;
            }
        }
        __syncthreads();

        float o[4][2];
#pragma unroll
        for (int i = 0; i < 4; i++) { o[i][0] = 0.f; o[i][1] = 0.f; }
#pragma unroll
        for (int j = 0; j < 64; j += 4) {
            const float4 v0 = *(const float4*)&Vs[tx * PST + j];
            const float4 v1 = *(const float4*)&Vs[(16 + tx) * PST + j];
#pragma unroll
            for (int i = 0; i < 4; i++) {
                const float4 p = *(const float4*)&Ps[(ty * 4 + i) * PST + j];
                o[i][0] += p.x * v0.x + p.y * v0.y + p.z * v0.z + p.w * v0.w;
                o[i][1] += p.x * v1.x + p.y * v1.y + p.z * v1.z + p.w * v1.w;
            }
        }
#pragma unroll
        for (int i = 0; i < 4; i++) {
            const int o2 = (ty * 4 + i) * NHEAD + h;
            Ob[(size_t)o2 * NSP + nb + tx]      = __float2half(o[i][0]);
            Ob[(size_t)o2 * NSP + nb + 16 + tx] = __float2half(o[i][1]);
        }
        __syncthreads();
    }
}

// ---------------------------------------------------------------------------
// Launch
// ---------------------------------------------------------------------------
extern "C" void kernel_launch(void* const* d_in, const int* in_sizes, int n_in,
                              void* d_out, int out_size)
{
    const float* x       = (const float*)d_in[0];
    const float* query   = (const float*)d_in[1];
    const float* key_w   = (const float*)d_in[2];
    const float* key_b   = (const float*)d_in[3];
    const float* query_w = (const float*)d_in[4];
    const float* query_b = (const float*)d_in[5];
    const float* val_w   = (const float*)d_in[6];
    const float* val_b   = (const float*)d_in[7];
    const float* up_w    = (const float*)d_in[8];
    const float* up_b    = (const float*)d_in[9];
    float* out = (float*)d_out;

    __half *khbuf, *qphbuf, *vhbuf, *ohbuf, *xhbuf, *qhbuf, *whbuf;
    float *spbuf, *pbuf;
    cudaGetSymbolAddress((void**)&khbuf, g_kh);
    cudaGetSymbolAddress((void**)&qphbuf, g_qph);
    cudaGetSymbolAddress((void**)&vhbuf, g_vh);
    cudaGetSymbolAddress((void**)&ohbuf, g_oh);
    cudaGetSymbolAddress((void**)&xhbuf, g_xh);
    cudaGetSymbolAddress((void**)&qhbuf, g_qh);
    cudaGetSymbolAddress((void**)&whbuf, g_wh);
    cudaGetSymbolAddress((void**)&spbuf, g_spart);
    cudaGetSymbolAddress((void**)&pbuf, g_p);

    cudaFuncSetAttribute(proj3_kernel,
                         cudaFuncAttributeMaxDynamicSharedMemorySize, GEMM_SMEM_BYTES);
    cudaFuncSetAttribute(up_kernel,
                         cudaFuncAttributeMaxDynamicSharedMemorySize, GEMM_SMEM_BYTES);

    // 1) fp32 -> fp16 conversions (single fused launch)
    convert_all_kernel<<<2048, 256>>>(x, query, xhbuf, qhbuf,
                                      key_w, query_w, val_w, up_w, whbuf);

    // 2) projections (fused, fp16 out)
    ProjArgs pa;
    pa.X[0] = xhbuf;    pa.X[1] = qhbuf;      pa.X[2] = xhbuf;
    pa.Y[0] = khbuf;    pa.Y[1] = qphbuf;     pa.Y[2] = vhbuf;
    pa.bias[0] = key_b; pa.bias[1] = query_b; pa.bias[2] = val_b;

    const dim3 gblk(GTHREADS);
    const dim3 grid_proj((NSP + 127) / 128, COUT / 128, 3 * B_);   // (13, 4, 96)
    const dim3 grid_up((NSP + 127) / 128, CIN / 128, B_);          // (13, 8, 32)

    proj3_kernel<<<grid_proj, gblk, GEMM_SMEM_BYTES>>>(pa, whbuf);

    // 3) attention: S partials (tensor cores) -> softmax -> O
    attn_s_kernel<<<dim3(B_ * NHEAD, NCHUNK), 128>>>(khbuf, qphbuf, spbuf);
    attn_softmax_kernel<<<B_ * NHEAD, 64>>>(spbuf, pbuf);
    attn_o_kernel<<<dim3(B_ * NHEAD, NCHUNK), 256>>>(pbuf, vhbuf, ohbuf);

    // 4) up projection (fp32 out)
    up_kernel<<<grid_up, gblk, GEMM_SMEM_BYTES>>>(whbuf, ohbuf, up_b, out);
}

// round 15
// speedup vs baseline: 1.0497x; 1.0497x over previous
#include <cuda_runtime.h>
#include <cuda_fp16.h>
#include <cstdint>

// Problem constants
#define B_   32
#define CIN  1024
#define COUT 512
#define NSP  1568          // T*H*W = 8*14*14
#define NHEAD 8
#define DK   64
#define NCHUNK 7
#define CHUNK 224          // 1568 / 7

// Scratch buffers (device globals: allocation-free contract)
__device__ __half g_kh[(size_t)B_ * COUT * NSP];
__device__ __half g_qph[(size_t)B_ * COUT * NSP];
__device__ __half g_vh[(size_t)B_ * COUT * NSP];
__device__ __half g_oh[(size_t)B_ * COUT * NSP];
__device__ __half g_xh[(size_t)B_ * CIN * NSP];
__device__ __half g_qh[(size_t)B_ * CIN * NSP];
__device__ __half g_wh[4 * 512 * 1024];          // key_w, query_w, val_w, up_w
__device__ float  g_spart[(size_t)B_ * NHEAD * NCHUNK * DK * DK];
__device__ float  g_p[(size_t)B_ * NHEAD * DK * DK];

// ---------------------------------------------------------------------------
// PTX helpers
// ---------------------------------------------------------------------------
__device__ __forceinline__ uint32_t smem_u32(const void* p) {
    uint32_t a;
    asm("{ .reg .u64 t; cvta.to.shared.u64 t, %1; cvt.u32.u64 %0, t; }"
        : "=r"(a) : "l"(p));
    return a;
}

__device__ __forceinline__ void cp16(uint32_t dst, const void* src, uint32_t srcsize) {
    asm volatile("cp.async.cg.shared.global [%0], [%1], 16, %2;"
                 :: "r"(dst), "l"(src), "r"(srcsize) : "memory");
}
#define CP_COMMIT() asm volatile("cp.async.commit_group;" ::: "memory")
#define CP_WAIT1()  asm volatile("cp.async.wait_group 1;" ::: "memory")

__device__ __forceinline__ void ldsm4(uint32_t* r, uint32_t addr) {
    asm volatile("ldmatrix.sync.aligned.m8n8.x4.shared.b16 {%0,%1,%2,%3}, [%4];"
                 : "=r"(r[0]), "=r"(r[1]), "=r"(r[2]), "=r"(r[3]) : "r"(addr));
}
__device__ __forceinline__ void ldsm4t(uint32_t* r, uint32_t addr) {
    asm volatile("ldmatrix.sync.aligned.m8n8.x4.trans.shared.b16 {%0,%1,%2,%3}, [%4];"
                 : "=r"(r[0]), "=r"(r[1]), "=r"(r[2]), "=r"(r[3]) : "r"(addr));
}

__device__ __forceinline__ void mma16(float* d, const uint32_t* a, const uint32_t* b) {
    asm volatile(
        "mma.sync.aligned.m16n8k16.row.col.f32.f16.f16.f32 "
        "{%0,%1,%2,%3},{%4,%5,%6,%7},{%8,%9},{%0,%1,%2,%3};"
        : "+f"(d[0]), "+f"(d[1]), "+f"(d[2]), "+f"(d[3])
        : "r"(a[0]), "r"(a[1]), "r"(a[2]), "r"(a[3]), "r"(b[0]), "r"(b[1]));
}

// ---------------------------------------------------------------------------
// FP16 GEMM: Y[m,n] = sum_k A[m,k]*B[k,n] + bias[m]     (R13 config)
// BM=BN=128, BK=64, 128 threads (4 warps 2m x 2n), warp tile 64x64.
// 3-stage cp.async pipeline; ldmatrix (A: 144B rows, B: 272B rows, both
// conflict-free). 2 CTAs/SM. M%128==0, K%64==0.
// ---------------------------------------------------------------------------
#define A_ROWB   144
#define B_ROWB   272
#define A_BYTES  (128 * A_ROWB)            // 18432
#define B_BYTES  (64 * B_ROWB)             // 17408
#define STAGE_B  (A_BYTES + B_BYTES)       // 35840
#define GEMM_SMEM_BYTES (3 * STAGE_B)      // 107520
#define GTHREADS 128

__device__ __forceinline__ void gemm_issue(
    const __half* __restrict__ A, const __half* __restrict__ B,
    int K, int N, int m0, int n0, int kt, uint32_t sbase, int tid)
{
    const uint32_t st = sbase + (kt % 3) * STAGE_B;
#pragma unroll
    for (int i = 0; i < 8; i++) {
        const int id = tid + GTHREADS * i;
        const int r = id >> 3, c = id & 7;
        cp16(st + r * A_ROWB + c * 16,
             A + (size_t)(m0 + r) * K + kt * 64 + c * 8, 16);
    }
#pragma unroll
    for (int i = 0; i < 8; i++) {
        const int id = tid + GTHREADS * i;
        const int k = id >> 4, c = id & 15;
        const int n = n0 + c * 8;
        cp16(st + A_BYTES + k * B_ROWB + c * 16,
             B + (size_t)(kt * 64 + k) * N + n, (n < N) ? 16u : 0u);
    }
}

template <bool HALF_OUT, typename OutT>
__device__ __forceinline__ void gemm_body(
    const __half* __restrict__ A, const __half* __restrict__ B,
    const float* __restrict__ bias, OutT* __restrict__ Y,
    int M, int N, int K, int m0, int n0, uint8_t* smem)
{
    const int tid  = threadIdx.x;
    const int lane = tid & 31;
    const int w    = tid >> 5;          // 0..3
    const int g    = lane >> 2;
    const int c    = lane & 3;
    const int wm   = (w & 1) << 6;      // 0/64
    const int wn   = (w >> 1) << 6;     // 0/64

    const uint32_t sbase = smem_u32(smem);
    const int KT = K >> 6;

    float acc[4][8][4];
#pragma unroll
    for (int mt = 0; mt < 4; mt++)
#pragma unroll
        for (int nt = 0; nt < 8; nt++)
#pragma unroll
            for (int r = 0; r < 4; r++) acc[mt][nt][r] = 0.f;

    const uint32_t a_addr = (uint32_t)((wm + (lane & 15)) * A_ROWB + (lane >> 4) * 16);
    const uint32_t b_addr = (uint32_t)(A_BYTES + (lane & 15) * B_ROWB
                                       + (wn + (lane >> 4) * 8) * 2);

    // prologue: 2 stages in flight
    gemm_issue(A, B, K, N, m0, n0, 0, sbase, tid); CP_COMMIT();
    if (KT > 1) gemm_issue(A, B, K, N, m0, n0, 1, sbase, tid);
    CP_COMMIT();

    for (int kt = 0; kt < KT; kt++) {
        CP_WAIT1();                 // stage kt resident
        __syncthreads();
        if (kt + 2 < KT) gemm_issue(A, B, K, N, m0, n0, kt + 2, sbase, tid);
        CP_COMMIT();

        const uint32_t st = sbase + (kt % 3) * STAGE_B;
#pragma unroll
        for (int ks = 0; ks < 4; ks++) {
            uint32_t af[4][4];
#pragma unroll
            for (int mt = 0; mt < 4; mt++)
                ldsm4(af[mt], st + a_addr + mt * 16 * A_ROWB + ks * 32);
            uint32_t bf[8][2];
#pragma unroll
            for (int p = 0; p < 4; p++) {
                uint32_t t[4];
                ldsm4t(t, st + b_addr + ks * 16 * B_ROWB + p * 32);
                bf[2 * p][0] = t[0]; bf[2 * p][1] = t[1];
                bf[2 * p + 1][0] = t[2]; bf[2 * p + 1][1] = t[3];
            }
#pragma unroll
            for (int mt = 0; mt < 4; mt++)
#pragma unroll
                for (int nt = 0; nt < 8; nt++)
                    mma16(acc[mt][nt], af[mt], bf[nt]);
        }
    }

    // ---- epilogue: bias + guarded stores ----
#pragma unroll
    for (int mt = 0; mt < 4; mt++) {
        const int mrow = m0 + wm + mt * 16 + g;
        const float bb0 = bias[mrow];
        const float bb1 = bias[mrow + 8];
#pragma unroll
        for (int nt = 0; nt < 8; nt++) {
            const int n = n0 + wn + nt * 8 + 2 * c;
            if (n < N) {
                if (HALF_OUT) {
                    __half2 h0 = __floats2half2_rn(acc[mt][nt][0] + bb0,
                                                   acc[mt][nt][1] + bb0);
                    __half2 h1 = __floats2half2_rn(acc[mt][nt][2] + bb1,
                                                   acc[mt][nt][3] + bb1);
                    *(__half2*)((__half*)Y + (size_t)mrow * N + n)       = h0;
                    *(__half2*)((__half*)Y + (size_t)(mrow + 8) * N + n) = h1;
                } else {
                    float2 o0, o1;
                    o0.x = acc[mt][nt][0] + bb0; o0.y = acc[mt][nt][1] + bb0;
                    o1.x = acc[mt][nt][2] + bb1; o1.y = acc[mt][nt][3] + bb1;
                    *(float2*)((float*)Y + (size_t)mrow * N + n)       = o0;
                    *(float2*)((float*)Y + (size_t)(mrow + 8) * N + n) = o1;
                }
            }
        }
    }
}

// ---------------------------------------------------------------------------
// Fused conversion kernel: inputs (x, query) + 4 weight matrices
// ---------------------------------------------------------------------------
__global__ void __launch_bounds__(256)
convert_all_kernel(const float* __restrict__ x, const float* __restrict__ q,
                   __half* __restrict__ xh, __half* __restrict__ qh,
                   const float* __restrict__ w0, const float* __restrict__ w1,
                   const float* __restrict__ w2, const float* __restrict__ w3,
                   __half* __restrict__ wdst)
{
    const size_t n4in = (size_t)B_ * CIN * NSP / 4;       // float4s per input
    const int    seg  = 512 * 1024 / 4;                   // float4s per weight
    const size_t total = 2 * n4in + 4 * (size_t)seg;
    const size_t stride = (size_t)gridDim.x * blockDim.x;
    for (size_t i = (size_t)blockIdx.x * blockDim.x + threadIdx.x; i < total; i += stride) {
        const float* src; __half* dst; size_t j;
        if (i < n4in)            { src = x; dst = xh; j = i; }
        else if (i < 2 * n4in)   { src = q; dst = qh; j = i - n4in; }
        else {
            size_t wi = i - 2 * n4in;
            const int which = (int)(wi / seg);
            j = wi % seg;
            src = (which == 0) ? w0 : (which == 1) ? w1 : (which == 2) ? w2 : w3;
            dst = wdst + (size_t)which * 512 * 1024;
        }
        float4 v = ((const float4*)src)[j];
        ((__half2*)dst)[2 * j]     = __floats2half2_rn(v.x, v.y);
        ((__half2*)dst)[2 * j + 1] = __floats2half2_rn(v.z, v.w);
    }
}

// ---------------------------------------------------------------------------
// GEMM launch wrappers
// ---------------------------------------------------------------------------
struct ProjArgs {
    const __half* X[3];
    __half*       Y[3];
    const float*  bias[3];
};

__global__ void __launch_bounds__(GTHREADS, 2)
proj3_kernel(ProjArgs pa, const __half* __restrict__ Wh)
{
    extern __shared__ uint8_t smem[];
    const int which = blockIdx.z % 3;
    const int b     = blockIdx.z / 3;
    gemm_body<true>(Wh + (size_t)which * 512 * 1024,
                    pa.X[which] + (size_t)b * CIN * NSP,
                    pa.bias[which],
                    pa.Y[which] + (size_t)b * COUT * NSP,
                    COUT, NSP, CIN, blockIdx.y * 128, blockIdx.x * 128, smem);
}

__global__ void __launch_bounds__(GTHREADS, 2)
up_kernel(const __half* __restrict__ Wh, const __half* __restrict__ X,
          const float* __restrict__ bias, float* __restrict__ Y)
{
    extern __shared__ uint8_t smem[];
    const int b = blockIdx.z;
    gemm_body<false>(Wh + (size_t)3 * 512 * 1024,
                     X + (size_t)b * COUT * NSP, bias, Y + (size_t)b * CIN * NSP,
                     CIN, NSP, COUT, blockIdx.y * 128, blockIdx.x * 128, smem);
}

// ---------------------------------------------------------------------------
// Attention — S via tensor cores (R13), softmax parallelized (new), O SIMT.
// ---------------------------------------------------------------------------
#define KST 72    // halves; 144B rows -> ldmatrix conflict-free

__global__ void __launch_bounds__(128)
attn_s_kernel(const __half* __restrict__ Kp, const __half* __restrict__ Qp,
              float* __restrict__ Sp)
{
    const int bh = blockIdx.x;
    const int ch = blockIdx.y;
    const int b = bh >> 3;
    const int h = bh & 7;
    const size_t base = (size_t)b * (COUT * NSP);
    const __half* Kb = Kp + base + h * DK;
    const __half* Qb = Qp + base + h * DK;

    __shared__ __half Ksm[32 * KST];
    __shared__ __half Qsm[32 * KST];
    const uint32_t ksb = smem_u32(Ksm);
    const uint32_t qsb = smem_u32(Qsm);

    const int tid  = threadIdx.x;
    const int lane = tid & 31;
    const int w    = tid >> 5;
    const int wm   = (w & 1) << 5;
    const int wn   = (w >> 1) << 5;

    float acc[2][4][4];
#pragma unroll
    for (int mt = 0; mt < 2; mt++)
#pragma unroll
        for (int nt = 0; nt < 4; nt++)
#pragma unroll
            for (int r = 0; r < 4; r++) acc[mt][nt][r] = 0.f;

    const int r  = tid >> 3;
    const int c8 = (tid & 7) << 3;

    const int n0 = ch * CHUNK;
    for (int nb = n0; nb < n0 + CHUNK; nb += 32) {
#pragma unroll
        for (int u = 0; u < 2; u++) {
            const int rr = r + u * 16;
            const size_t gg = (size_t)(nb + rr) * COUT + c8;
            *(uint4*)&Ksm[rr * KST + c8] = *(const uint4*)&Kb[gg];
            *(uint4*)&Qsm[rr * KST + c8] = *(const uint4*)&Qb[gg];
        }
        __syncthreads();

#pragma unroll
        for (int s = 0; s < 2; s++) {
            const uint32_t krow = (uint32_t)((s * 16 + (lane & 15)) * KST * 2);
            const uint32_t cblk = (uint32_t)((lane >> 4) * 8 * 2);
            uint32_t t[4];
            uint32_t af[2][4];
#pragma unroll
            for (int mt = 0; mt < 2; mt++) {
                ldsm4t(t, ksb + krow + (uint32_t)((wm + mt * 16) * 2) + cblk);
                af[mt][0] = t[0]; af[mt][1] = t[2];
                af[mt][2] = t[1]; af[mt][3] = t[3];
            }
            uint32_t bf[4][2];
#pragma unroll
            for (int p = 0; p < 2; p++) {
                ldsm4t(t, qsb + krow + (uint32_t)((wn + p * 16) * 2) + cblk);
                bf[2 * p][0] = t[0]; bf[2 * p][1] = t[1];
                bf[2 * p + 1][0] = t[2]; bf[2 * p + 1][1] = t[3];
            }
#pragma unroll
            for (int mt = 0; mt < 2; mt++)
#pragma unroll
                for (int nt = 0; nt < 4; nt++)
                    mma16(acc[mt][nt], af[mt], bf[nt]);
        }
        __syncthreads();
    }

    float* out = Sp + ((size_t)bh * NCHUNK + ch) * (DK * DK);
    const int g = lane >> 2, cc = lane & 3;
#pragma unroll
    for (int mt = 0; mt < 2; mt++) {
        const int i0 = wm + mt * 16 + g;
#pragma unroll
        for (int nt = 0; nt < 4; nt++) {
            const int j = wn + nt * 8 + 2 * cc;
            float2 d0, d1;
            d0.x = acc[mt][nt][0]; d0.y = acc[mt][nt][1];
            d1.x = acc[mt][nt][2]; d1.y = acc[mt][nt][3];
            *(float2*)&out[i0 * DK + j]       = d0;
            *(float2*)&out[(i0 + 8) * DK + j] = d1;
        }
    }
}

// Softmax: grid 256, block 256. 4 threads per row; each handles 16 columns
// (4 float4s). Quad reduction via shfl_xor(1), shfl_xor(2).
__global__ void __launch_bounds__(256)
attn_softmax_kernel(const float* __restrict__ Sp, float* __restrict__ P)
{
    const int bh = blockIdx.x;
    const int i  = threadIdx.x >> 2;          // row 0..63
    const int q  = threadIdx.x & 3;           // quad lane: columns q*16..q*16+15

    const float* sp = Sp + (size_t)bh * NCHUNK * DK * DK + i * DK + q * 16;
    float4 s[4];
#pragma unroll
    for (int v = 0; v < 4; v++) s[v] = ((const float4*)sp)[v];
    for (int c = 1; c < NCHUNK; c++) {
        const float4* qq = (const float4*)(sp + c * DK * DK);
#pragma unroll
        for (int v = 0; v < 4; v++) {
            float4 t = qq[v];
            s[v].x += t.x; s[v].y += t.y; s[v].z += t.z; s[v].w += t.w;
        }
    }
    float mx = -1e30f;
#pragma unroll
    for (int v = 0; v < 4; v++) {
        s[v].x *= 0.125f; s[v].y *= 0.125f; s[v].z *= 0.125f; s[v].w *= 0.125f;
        mx = fmaxf(mx, fmaxf(fmaxf(s[v].x, s[v].y), fmaxf(s[v].z, s[v].w)));
    }
    mx = fmaxf(mx, __shfl_xor_sync(0xffffffffu, mx, 1));
    mx = fmaxf(mx, __shfl_xor_sync(0xffffffffu, mx, 2));

    float sum = 0.f;
#pragma unroll
    for (int v = 0; v < 4; v++) {
        s[v].x = expf(s[v].x - mx); s[v].y = expf(s[v].y - mx);
        s[v].z = expf(s[v].z - mx); s[v].w = expf(s[v].w - mx);
        sum += s[v].x + s[v].y + s[v].z + s[v].w;
    }
    sum += __shfl_xor_sync(0xffffffffu, sum, 1);
    sum += __shfl_xor_sync(0xffffffffu, sum, 2);
    const float inv = 1.0f / sum;

    float* out = P + (size_t)bh * DK * DK + i * DK + q * 16;
#pragma unroll
    for (int v = 0; v < 4; v++) {
        float4 o;
        o.x = s[v].x * inv; o.y = s[v].y * inv;
        o.z = s[v].z * inv; o.w = s[v].w * inv;
        ((float4*)out)[v] = o;
    }
}

#define PST 68    // floats; 272B rows, float4-aligned
__global__ void __launch_bounds__(256)
attn_o_kernel(const float* __restrict__ P, const __half* __restrict__ Vp,
              __half* __restrict__ Op)
{
    const int bh = blockIdx.x;
    const int ch = blockIdx.y;
    const int b = bh >> 3;
    const int h = bh & 7;
    const size_t base = (size_t)b * (COUT * NSP);
    const __half* Vb = Vp + base + h * DK;
    __half*       Ob = Op + base;

    __shared__ float Ps[64 * PST];
    __shared__ float Vs[32 * PST];

    const int tid = threadIdx.x;
    const int tx = tid & 15;
    const int ty = tid >> 4;

    {
        const float* p = P + (size_t)bh * DK * DK;
#pragma unroll
        for (int u = 0; u < 4; u++) {
            const int idx = tid + u * 256;
            const int row = idx >> 4;
            const int c4  = (idx & 15) << 2;
            *(float4*)&Ps[row * PST + c4] = *(const float4*)&p[row * DK + c4];
        }
    }
    __syncthreads();

    const int r  = tid >> 3;
    const int c8 = (tid & 7) << 3;

    const int n0 = ch * CHUNK;
    for (int nb = n0; nb < n0 + CHUNK; nb += 32) {
        {
            uint4 u = *(const uint4*)&Vb[(size_t)(nb + r) * COUT + c8];
            const __half2* h2 = (const __half2*)&u;
#pragma unroll
            for (int q = 0; q < 4; q++) {
                float2 f = __half22float2(h2[q]);
                Vs[r * PST + c8 + 2 * q]     = f.x;
                Vs[r * PST + c8 + 2 * q + 1] = f.y;
            }
        }
        __syncthreads();

        float o[4][2];
#pragma unroll
        for (int i = 0; i < 4; i++) { o[i][0] = 0.f; o[i][1] = 0.f; }
#pragma unroll
        for (int j = 0; j < 64; j += 4) {
            const float4 v0 = *(const float4*)&Vs[tx * PST + j];
            const float4 v1 = *(const float4*)&Vs[(16 + tx) * PST + j];
#pragma unroll
            for (int i = 0; i < 4; i++) {
                const float4 p = *(const float4*)&Ps[(ty * 4 + i) * PST + j];
                o[i][0] += p.x * v0.x + p.y * v0.y + p.z * v0.z + p.w * v0.w;
                o[i][1] += p.x * v1.x + p.y * v1.y + p.z * v1.z + p.w * v1.w;
            }
        }
#pragma unroll
        for (int i = 0; i < 4; i++) {
            const int o2 = (ty * 4 + i) * NHEAD + h;
            Ob[(size_t)o2 * NSP + nb + tx]      = __float2half(o[i][0]);
            Ob[(size_t)o2 * NSP + nb + 16 + tx] = __float2half(o[i][1]);
        }
        __syncthreads();
    }
}

// ---------------------------------------------------------------------------
// Launch
// ---------------------------------------------------------------------------
extern "C" void kernel_launch(void* const* d_in, const int* in_sizes, int n_in,
                              void* d_out, int out_size)
{
    const float* x       = (const float*)d_in[0];
    const float* query   = (const float*)d_in[1];
    const float* key_w   = (const float*)d_in[2];
    const float* key_b   = (const float*)d_in[3];
    const float* query_w = (const float*)d_in[4];
    const float* query_b = (const float*)d_in[5];
    const float* val_w   = (const float*)d_in[6];
    const float* val_b   = (const float*)d_in[7];
    const float* up_w    = (const float*)d_in[8];
    const float* up_b    = (const float*)d_in[9];
    float* out = (float*)d_out;

    __half *khbuf, *qphbuf, *vhbuf, *ohbuf, *xhbuf, *qhbuf, *whbuf;
    float *spbuf, *pbuf;
    cudaGetSymbolAddress((void**)&khbuf, g_kh);
    cudaGetSymbolAddress((void**)&qphbuf, g_qph);
    cudaGetSymbolAddress((void**)&vhbuf, g_vh);
    cudaGetSymbolAddress((void**)&ohbuf, g_oh);
    cudaGetSymbolAddress((void**)&xhbuf, g_xh);
    cudaGetSymbolAddress((void**)&qhbuf, g_qh);
    cudaGetSymbolAddress((void**)&whbuf, g_wh);
    cudaGetSymbolAddress((void**)&spbuf, g_spart);
    cudaGetSymbolAddress((void**)&pbuf, g_p);

    cudaFuncSetAttribute(proj3_kernel,
                         cudaFuncAttributeMaxDynamicSharedMemorySize, GEMM_SMEM_BYTES);
    cudaFuncSetAttribute(up_kernel,
                         cudaFuncAttributeMaxDynamicSharedMemorySize, GEMM_SMEM_BYTES);

    // 1) fp32 -> fp16 conversions (single fused launch)
    convert_all_kernel<<<2048, 256>>>(x, query, xhbuf, qhbuf,
                                      key_w, query_w, val_w, up_w, whbuf);

    // 2) projections (fused, fp16 out)
    ProjArgs pa;
    pa.X[0] = xhbuf;    pa.X[1] = qhbuf;      pa.X[2] = xhbuf;
    pa.Y[0] = khbuf;    pa.Y[1] = qphbuf;     pa.Y[2] = vhbuf;
    pa.bias[0] = key_b; pa.bias[1] = query_b; pa.bias[2] = val_b;

    const dim3 gblk(GTHREADS);
    const dim3 grid_proj((NSP + 127) / 128, COUT / 128, 3 * B_);   // (13, 4, 96)
    const dim3 grid_up((NSP + 127) / 128, CIN / 128, B_);          // (13, 8, 32)

    proj3_kernel<<<grid_proj, gblk, GEMM_SMEM_BYTES>>>(pa, whbuf);

    // 3) attention: S partials (tensor cores) -> softmax -> O
    attn_s_kernel<<<dim3(B_ * NHEAD, NCHUNK), 128>>>(khbuf, qphbuf, spbuf);
    attn_softmax_kernel<<<B_ * NHEAD, 256>>>(spbuf, pbuf);
    attn_o_kernel<<<dim3(B_ * NHEAD, NCHUNK), 256>>>(pbuf, vhbuf, ohbuf);

    // 4) up projection (fp32 out)
    up_kernel<<<grid_up, gblk, GEMM_SMEM_BYTES>>>(whbuf, ohbuf, up_b, out);
}

// round 16
// speedup vs baseline: 1.0501x; 1.0004x over previous
#include <cuda_runtime.h>
#include <cuda_fp16.h>
#include <cstdint>

// Problem constants
#define B_   32
#define CIN  1024
#define COUT 512
#define NSP  1568          // T*H*W = 8*14*14
#define NHEAD 8
#define DK   64
#define NCHUNK_S 13        // attn_s: 128-row chunks (last = 32 rows)
#define NCHUNK_O 7         // attn_o: 224-row chunks
#define CHUNK_O  224

// Scratch buffers (device globals: allocation-free contract)
__device__ __half g_kh[(size_t)B_ * COUT * NSP];
__device__ __half g_qph[(size_t)B_ * COUT * NSP];
__device__ __half g_vh[(size_t)B_ * COUT * NSP];
__device__ __half g_oh[(size_t)B_ * COUT * NSP];
__device__ __half g_xh[(size_t)B_ * CIN * NSP];
__device__ __half g_qh[(size_t)B_ * CIN * NSP];
__device__ __half g_wh[4 * 512 * 1024];          // key_w, query_w, val_w, up_w
__device__ float  g_spart[(size_t)B_ * NHEAD * NCHUNK_S * DK * DK];
__device__ float  g_p[(size_t)B_ * NHEAD * DK * DK];

// ---------------------------------------------------------------------------
// PTX helpers
// ---------------------------------------------------------------------------
__device__ __forceinline__ uint32_t smem_u32(const void* p) {
    uint32_t a;
    asm("{ .reg .u64 t; cvta.to.shared.u64 t, %1; cvt.u32.u64 %0, t; }"
        : "=r"(a) : "l"(p));
    return a;
}

__device__ __forceinline__ void cp16(uint32_t dst, const void* src, uint32_t srcsize) {
    asm volatile("cp.async.cg.shared.global [%0], [%1], 16, %2;"
                 :: "r"(dst), "l"(src), "r"(srcsize) : "memory");
}
#define CP_COMMIT() asm volatile("cp.async.commit_group;" ::: "memory")
#define CP_WAIT1()  asm volatile("cp.async.wait_group 1;" ::: "memory")

__device__ __forceinline__ void ldsm4(uint32_t* r, uint32_t addr) {
    asm volatile("ldmatrix.sync.aligned.m8n8.x4.shared.b16 {%0,%1,%2,%3}, [%4];"
                 : "=r"(r[0]), "=r"(r[1]), "=r"(r[2]), "=r"(r[3]) : "r"(addr));
}
__device__ __forceinline__ void ldsm4t(uint32_t* r, uint32_t addr) {
    asm volatile("ldmatrix.sync.aligned.m8n8.x4.trans.shared.b16 {%0,%1,%2,%3}, [%4];"
                 : "=r"(r[0]), "=r"(r[1]), "=r"(r[2]), "=r"(r[3]) : "r"(addr));
}

__device__ __forceinline__ void mma16(float* d, const uint32_t* a, const uint32_t* b) {
    asm volatile(
        "mma.sync.aligned.m16n8k16.row.col.f32.f16.f16.f32 "
        "{%0,%1,%2,%3},{%4,%5,%6,%7},{%8,%9},{%0,%1,%2,%3};"
        : "+f"(d[0]), "+f"(d[1]), "+f"(d[2]), "+f"(d[3])
        : "r"(a[0]), "r"(a[1]), "r"(a[2]), "r"(a[3]), "r"(b[0]), "r"(b[1]));
}

// ---------------------------------------------------------------------------
// FP16 GEMM: Y[m,n] = sum_k A[m,k]*B[k,n] + bias[m]     (R13 config, frozen)
// BM=BN=128, BK=64, 128 threads (4 warps 2m x 2n), warp tile 64x64.
// 3-stage cp.async pipeline; ldmatrix (A: 144B rows, B: 272B rows, both
// conflict-free). 2 CTAs/SM. M%128==0, K%64==0.
// ---------------------------------------------------------------------------
#define A_ROWB   144
#define B_ROWB   272
#define A_BYTES  (128 * A_ROWB)            // 18432
#define B_BYTES  (64 * B_ROWB)             // 17408
#define STAGE_B  (A_BYTES + B_BYTES)       // 35840
#define GEMM_SMEM_BYTES (3 * STAGE_B)      // 107520
#define GTHREADS 128

__device__ __forceinline__ void gemm_issue(
    const __half* __restrict__ A, const __half* __restrict__ B,
    int K, int N, int m0, int n0, int kt, uint32_t sbase, int tid)
{
    const uint32_t st = sbase + (kt % 3) * STAGE_B;
#pragma unroll
    for (int i = 0; i < 8; i++) {
        const int id = tid + GTHREADS * i;
        const int r = id >> 3, c = id & 7;
        cp16(st + r * A_ROWB + c * 16,
             A + (size_t)(m0 + r) * K + kt * 64 + c * 8, 16);
    }
#pragma unroll
    for (int i = 0; i < 8; i++) {
        const int id = tid + GTHREADS * i;
        const int k = id >> 4, c = id & 15;
        const int n = n0 + c * 8;
        cp16(st + A_BYTES + k * B_ROWB + c * 16,
             B + (size_t)(kt * 64 + k) * N + n, (n < N) ? 16u : 0u);
    }
}

template <bool HALF_OUT, typename OutT>
__device__ __forceinline__ void gemm_body(
    const __half* __restrict__ A, const __half* __restrict__ B,
    const float* __restrict__ bias, OutT* __restrict__ Y,
    int M, int N, int K, int m0, int n0, uint8_t* smem)
{
    const int tid  = threadIdx.x;
    const int lane = tid & 31;
    const int w    = tid >> 5;          // 0..3
    const int g    = lane >> 2;
    const int c    = lane & 3;
    const int wm   = (w & 1) << 6;      // 0/64
    const int wn   = (w >> 1) << 6;     // 0/64

    const uint32_t sbase = smem_u32(smem);
    const int KT = K >> 6;

    float acc[4][8][4];
#pragma unroll
    for (int mt = 0; mt < 4; mt++)
#pragma unroll
        for (int nt = 0; nt < 8; nt++)
#pragma unroll
            for (int r = 0; r < 4; r++) acc[mt][nt][r] = 0.f;

    const uint32_t a_addr = (uint32_t)((wm + (lane & 15)) * A_ROWB + (lane >> 4) * 16);
    const uint32_t b_addr = (uint32_t)(A_BYTES + (lane & 15) * B_ROWB
                                       + (wn + (lane >> 4) * 8) * 2);

    // prologue: 2 stages in flight
    gemm_issue(A, B, K, N, m0, n0, 0, sbase, tid); CP_COMMIT();
    if (KT > 1) gemm_issue(A, B, K, N, m0, n0, 1, sbase, tid);
    CP_COMMIT();

    for (int kt = 0; kt < KT; kt++) {
        CP_WAIT1();                 // stage kt resident
        __syncthreads();
        if (kt + 2 < KT) gemm_issue(A, B, K, N, m0, n0, kt + 2, sbase, tid);
        CP_COMMIT();

        const uint32_t st = sbase + (kt % 3) * STAGE_B;
#pragma unroll
        for (int ks = 0; ks < 4; ks++) {
            uint32_t af[4][4];
#pragma unroll
            for (int mt = 0; mt < 4; mt++)
                ldsm4(af[mt], st + a_addr + mt * 16 * A_ROWB + ks * 32);
            uint32_t bf[8][2];
#pragma unroll
            for (int p = 0; p < 4; p++) {
                uint32_t t[4];
                ldsm4t(t, st + b_addr + ks * 16 * B_ROWB + p * 32);
                bf[2 * p][0] = t[0]; bf[2 * p][1] = t[1];
                bf[2 * p + 1][0] = t[2]; bf[2 * p + 1][1] = t[3];
            }
#pragma unroll
            for (int mt = 0; mt < 4; mt++)
#pragma unroll
                for (int nt = 0; nt < 8; nt++)
                    mma16(acc[mt][nt], af[mt], bf[nt]);
        }
    }

    // ---- epilogue: bias + guarded stores ----
#pragma unroll
    for (int mt = 0; mt < 4; mt++) {
        const int mrow = m0 + wm + mt * 16 + g;
        const float bb0 = bias[mrow];
        const float bb1 = bias[mrow + 8];
#pragma unroll
        for (int nt = 0; nt < 8; nt++) {
            const int n = n0 + wn + nt * 8 + 2 * c;
            if (n < N) {
                if (HALF_OUT) {
                    __half2 h0 = __floats2half2_rn(acc[mt][nt][0] + bb0,
                                                   acc[mt][nt][1] + bb0);
                    __half2 h1 = __floats2half2_rn(acc[mt][nt][2] + bb1,
                                                   acc[mt][nt][3] + bb1);
                    *(__half2*)((__half*)Y + (size_t)mrow * N + n)       = h0;
                    *(__half2*)((__half*)Y + (size_t)(mrow + 8) * N + n) = h1;
                } else {
                    float2 o0, o1;
                    o0.x = acc[mt][nt][0] + bb0; o0.y = acc[mt][nt][1] + bb0;
                    o1.x = acc[mt][nt][2] + bb1; o1.y = acc[mt][nt][3] + bb1;
                    *(float2*)((float*)Y + (size_t)mrow * N + n)       = o0;
                    *(float2*)((float*)Y + (size_t)(mrow + 8) * N + n) = o1;
                }
            }
        }
    }
}

// ---------------------------------------------------------------------------
// Fused conversion kernel: inputs (x, query) + 4 weight matrices
// ---------------------------------------------------------------------------
__global__ void __launch_bounds__(256)
convert_all_kernel(const float* __restrict__ x, const float* __restrict__ q,
                   __half* __restrict__ xh, __half* __restrict__ qh,
                   const float* __restrict__ w0, const float* __restrict__ w1,
                   const float* __restrict__ w2, const float* __restrict__ w3,
                   __half* __restrict__ wdst)
{
    const size_t n4in = (size_t)B_ * CIN * NSP / 4;       // float4s per input
    const int    seg  = 512 * 1024 / 4;                   // float4s per weight
    const size_t total = 2 * n4in + 4 * (size_t)seg;
    const size_t stride = (size_t)gridDim.x * blockDim.x;
    for (size_t i = (size_t)blockIdx.x * blockDim.x + threadIdx.x; i < total; i += stride) {
        const float* src; __half* dst; size_t j;
        if (i < n4in)            { src = x; dst = xh; j = i; }
        else if (i < 2 * n4in)   { src = q; dst = qh; j = i - n4in; }
        else {
            size_t wi = i - 2 * n4in;
            const int which = (int)(wi / seg);
            j = wi % seg;
            src = (which == 0) ? w0 : (which == 1) ? w1 : (which == 2) ? w2 : w3;
            dst = wdst + (size_t)which * 512 * 1024;
        }
        float4 v = ((const float4*)src)[j];
        ((__half2*)dst)[2 * j]     = __floats2half2_rn(v.x, v.y);
        ((__half2*)dst)[2 * j + 1] = __floats2half2_rn(v.z, v.w);
    }
}

// ---------------------------------------------------------------------------
// GEMM launch wrappers
// ---------------------------------------------------------------------------
struct ProjArgs {
    const __half* X[3];
    __half*       Y[3];
    const float*  bias[3];
};

__global__ void __launch_bounds__(GTHREADS, 2)
proj3_kernel(ProjArgs pa, const __half* __restrict__ Wh)
{
    extern __shared__ uint8_t smem[];
    const int which = blockIdx.z % 3;
    const int b     = blockIdx.z / 3;
    gemm_body<true>(Wh + (size_t)which * 512 * 1024,
                    pa.X[which] + (size_t)b * CIN * NSP,
                    pa.bias[which],
                    pa.Y[which] + (size_t)b * COUT * NSP,
                    COUT, NSP, CIN, blockIdx.y * 128, blockIdx.x * 128, smem);
}

__global__ void __launch_bounds__(GTHREADS, 2)
up_kernel(const __half* __restrict__ Wh, const __half* __restrict__ X,
          const float* __restrict__ bias, float* __restrict__ Y)
{
    extern __shared__ uint8_t smem[];
    const int b = blockIdx.z;
    gemm_body<false>(Wh + (size_t)3 * 512 * 1024,
                     X + (size_t)b * COUT * NSP, bias, Y + (size_t)b * CIN * NSP,
                     CIN, NSP, COUT, blockIdx.y * 128, blockIdx.x * 128, smem);
}

// ---------------------------------------------------------------------------
// Attention — S via tensor cores (double-buffered tiles, 13 chunks),
// parallel softmax (13 partials), O SIMT (double-buffered V tiles).
// K/Q/V fp16, layout [n][512], head h at column h*64.
// ---------------------------------------------------------------------------
#define KST 72    // halves; 144B rows -> ldmatrix conflict-free

__global__ void __launch_bounds__(128)
attn_s_kernel(const __half* __restrict__ Kp, const __half* __restrict__ Qp,
              float* __restrict__ Sp)
{
    const int bh = blockIdx.x;
    const int ch = blockIdx.y;
    const int b = bh >> 3;
    const int h = bh & 7;
    const size_t base = (size_t)b * (COUT * NSP);
    const __half* Kb = Kp + base + h * DK;
    const __half* Qb = Qp + base + h * DK;

    __shared__ __half Ksm[2][32 * KST];
    __shared__ __half Qsm[2][32 * KST];
    const uint32_t ksb = smem_u32(Ksm);
    const uint32_t qsb = smem_u32(Qsm);

    const int tid  = threadIdx.x;
    const int lane = tid & 31;
    const int w    = tid >> 5;
    const int wm   = (w & 1) << 5;
    const int wn   = (w >> 1) << 5;

    float acc[2][4][4];
#pragma unroll
    for (int mt = 0; mt < 2; mt++)
#pragma unroll
        for (int nt = 0; nt < 4; nt++)
#pragma unroll
            for (int r = 0; r < 4; r++) acc[mt][nt][r] = 0.f;

    const int r  = tid >> 3;             // 0..15
    const int c8 = (tid & 7) << 3;       // 0..56

    const int n0 = ch * 128;
    const int n1 = (n0 + 128 < NSP) ? (n0 + 128) : NSP;

    uint4 kr[2], qr[2];
    // fetch tile n0
#pragma unroll
    for (int u = 0; u < 2; u++) {
        const size_t gg = (size_t)(n0 + r + u * 16) * COUT + c8;
        kr[u] = *(const uint4*)&Kb[gg];
        qr[u] = *(const uint4*)&Qb[gg];
    }
    // stage into buf 0
#pragma unroll
    for (int u = 0; u < 2; u++) {
        *(uint4*)&Ksm[0][(r + u * 16) * KST + c8] = kr[u];
        *(uint4*)&Qsm[0][(r + u * 16) * KST + c8] = qr[u];
    }
    __syncthreads();

    int it = 0;
    for (int nb = n0; nb < n1; nb += 32, it++) {
        const int cur = it & 1;
        const bool more = (nb + 32 < n1);
        if (more) {
#pragma unroll
            for (int u = 0; u < 2; u++) {
                const size_t gg = (size_t)(nb + 32 + r + u * 16) * COUT + c8;
                kr[u] = *(const uint4*)&Kb[gg];
                qr[u] = *(const uint4*)&Qb[gg];
            }
        }

        const uint32_t kb = ksb + (uint32_t)(cur * 32 * KST * 2);
        const uint32_t qb = qsb + (uint32_t)(cur * 32 * KST * 2);
#pragma unroll
        for (int s = 0; s < 2; s++) {
            const uint32_t krow = (uint32_t)((s * 16 + (lane & 15)) * KST * 2);
            const uint32_t cblk = (uint32_t)((lane >> 4) * 8 * 2);
            uint32_t t[4];
            uint32_t af[2][4];
#pragma unroll
            for (int mt = 0; mt < 2; mt++) {
                ldsm4t(t, kb + krow + (uint32_t)((wm + mt * 16) * 2) + cblk);
                af[mt][0] = t[0]; af[mt][1] = t[2];
                af[mt][2] = t[1]; af[mt][3] = t[3];
            }
            uint32_t bf[4][2];
#pragma unroll
            for (int p = 0; p < 2; p++) {
                ldsm4t(t, qb + krow + (uint32_t)((wn + p * 16) * 2) + cblk);
                bf[2 * p][0] = t[0]; bf[2 * p][1] = t[1];
                bf[2 * p + 1][0] = t[2]; bf[2 * p + 1][1] = t[3];
            }
#pragma unroll
            for (int mt = 0; mt < 2; mt++)
#pragma unroll
                for (int nt = 0; nt < 4; nt++)
                    mma16(acc[mt][nt], af[mt], bf[nt]);
        }

        if (more) {
            const int nxt = cur ^ 1;
#pragma unroll
            for (int u = 0; u < 2; u++) {
                *(uint4*)&Ksm[nxt][(r + u * 16) * KST + c8] = kr[u];
                *(uint4*)&Qsm[nxt][(r + u * 16) * KST + c8] = qr[u];
            }
        }
        __syncthreads();
    }

    float* out = Sp + ((size_t)bh * NCHUNK_S + ch) * (DK * DK);
    const int g = lane >> 2, cc = lane & 3;
#pragma unroll
    for (int mt = 0; mt < 2; mt++) {
        const int i0 = wm + mt * 16 + g;
#pragma unroll
        for (int nt = 0; nt < 4; nt++) {
            const int j = wn + nt * 8 + 2 * cc;
            float2 d0, d1;
            d0.x = acc[mt][nt][0]; d0.y = acc[mt][nt][1];
            d1.x = acc[mt][nt][2]; d1.y = acc[mt][nt][3];
            *(float2*)&out[i0 * DK + j]       = d0;
            *(float2*)&out[(i0 + 8) * DK + j] = d1;
        }
    }
}

// Softmax: grid 256, block 256. 4 threads per row; 16 cols each.
__global__ void __launch_bounds__(256)
attn_softmax_kernel(const float* __restrict__ Sp, float* __restrict__ P)
{
    const int bh = blockIdx.x;
    const int i  = threadIdx.x >> 2;
    const int q  = threadIdx.x & 3;

    const float* sp = Sp + (size_t)bh * NCHUNK_S * DK * DK + i * DK + q * 16;
    float4 s[4];
#pragma unroll
    for (int v = 0; v < 4; v++) s[v] = ((const float4*)sp)[v];
    for (int c = 1; c < NCHUNK_S; c++) {
        const float4* qq = (const float4*)(sp + c * DK * DK);
#pragma unroll
        for (int v = 0; v < 4; v++) {
            float4 t = qq[v];
            s[v].x += t.x; s[v].y += t.y; s[v].z += t.z; s[v].w += t.w;
        }
    }
    float mx = -1e30f;
#pragma unroll
    for (int v = 0; v < 4; v++) {
        s[v].x *= 0.125f; s[v].y *= 0.125f; s[v].z *= 0.125f; s[v].w *= 0.125f;
        mx = fmaxf(mx, fmaxf(fmaxf(s[v].x, s[v].y), fmaxf(s[v].z, s[v].w)));
    }
    mx = fmaxf(mx, __shfl_xor_sync(0xffffffffu, mx, 1));
    mx = fmaxf(mx, __shfl_xor_sync(0xffffffffu, mx, 2));

    float sum = 0.f;
#pragma unroll
    for (int v = 0; v < 4; v++) {
        s[v].x = expf(s[v].x - mx); s[v].y = expf(s[v].y - mx);
        s[v].z = expf(s[v].z - mx); s[v].w = expf(s[v].w - mx);
        sum += s[v].x + s[v].y + s[v].z + s[v].w;
    }
    sum += __shfl_xor_sync(0xffffffffu, sum, 1);
    sum += __shfl_xor_sync(0xffffffffu, sum, 2);
    const float inv = 1.0f / sum;

    float* out = P + (size_t)bh * DK * DK + i * DK + q * 16;
#pragma unroll
    for (int v = 0; v < 4; v++) {
        float4 o;
        o.x = s[v].x * inv; o.y = s[v].y * inv;
        o.z = s[v].z * inv; o.w = s[v].w * inv;
        ((float4*)out)[v] = o;
    }
}

#define PST 68    // floats; 272B rows, float4-aligned
__global__ void __launch_bounds__(256)
attn_o_kernel(const float* __restrict__ P, const __half* __restrict__ Vp,
              __half* __restrict__ Op)
{
    const int bh = blockIdx.x;
    const int ch = blockIdx.y;
    const int b = bh >> 3;
    const int h = bh & 7;
    const size_t base = (size_t)b * (COUT * NSP);
    const __half* Vb = Vp + base + h * DK;
    __half*       Ob = Op + base;

    __shared__ float Ps[64 * PST];
    __shared__ float Vs[2][32 * PST];

    const int tid = threadIdx.x;
    const int tx = tid & 15;
    const int ty = tid >> 4;

    {
        const float* p = P + (size_t)bh * DK * DK;
#pragma unroll
        for (int u = 0; u < 4; u++) {
            const int idx = tid + u * 256;
            const int row = idx >> 4;
            const int c4  = (idx & 15) << 2;
            *(float4*)&Ps[row * PST + c4] = *(const float4*)&p[row * DK + c4];
        }
    }

    const int r  = tid >> 3;          // 0..31
    const int c8 = (tid & 7) << 3;    // 0..56

    const int n0 = ch * CHUNK_O;

    // fetch + stage tile n0 into buf 0
    uint4 vr = *(const uint4*)&Vb[(size_t)(n0 + r) * COUT + c8];
    {
        const __half2* h2 = (const __half2*)&vr;
#pragma unroll
        for (int q = 0; q < 4; q++) {
            float2 f = __half22float2(h2[q]);
            Vs[0][r * PST + c8 + 2 * q]     = f.x;
            Vs[0][r * PST + c8 + 2 * q + 1] = f.y;
        }
    }
    __syncthreads();

    int it = 0;
    for (int nb = n0; nb < n0 + CHUNK_O; nb += 32, it++) {
        const int cur = it & 1;
        const bool more = (nb + 32 < n0 + CHUNK_O);
        if (more)
            vr = *(const uint4*)&Vb[(size_t)(nb + 32 + r) * COUT + c8];

        float o[4][2];
#pragma unroll
        for (int i = 0; i < 4; i++) { o[i][0] = 0.f; o[i][1] = 0.f; }
#pragma unroll
        for (int j = 0; j < 64; j += 4) {
            const float4 v0 = *(const float4*)&Vs[cur][tx * PST + j];
            const float4 v1 = *(const float4*)&Vs[cur][(16 + tx) * PST + j];
#pragma unroll
            for (int i = 0; i < 4; i++) {
                const float4 p = *(const float4*)&Ps[(ty * 4 + i) * PST + j];
                o[i][0] += p.x * v0.x + p.y * v0.y + p.z * v0.z + p.w * v0.w;
                o[i][1] += p.x * v1.x + p.y * v1.y + p.z * v1.z + p.w * v1.w;
            }
        }
#pragma unroll
        for (int i = 0; i < 4; i++) {
            const int o2 = (ty * 4 + i) * NHEAD + h;
            Ob[(size_t)o2 * NSP + nb + tx]      = __float2half(o[i][0]);
            Ob[(size_t)o2 * NSP + nb + 16 + tx] = __float2half(o[i][1]);
        }

        if (more) {
            const int nxt = cur ^ 1;
            const __half2* h2 = (const __half2*)&vr;
#pragma unroll
            for (int q = 0; q < 4; q++) {
                float2 f = __half22float2(h2[q]);
                Vs[nxt][r * PST + c8 + 2 * q]     = f.x;
                Vs[nxt][r * PST + c8 + 2 * q + 1] = f.y;
            }
        }
        __syncthreads();
    }
}

// ---------------------------------------------------------------------------
// Launch
// ---------------------------------------------------------------------------
extern "C" void kernel_launch(void* const* d_in, const int* in_sizes, int n_in,
                              void* d_out, int out_size)
{
    const float* x       = (const float*)d_in[0];
    const float* query   = (const float*)d_in[1];
    const float* key_w   = (const float*)d_in[2];
    const float* key_b   = (const float*)d_in[3];
    const float* query_w = (const float*)d_in[4];
    const float* query_b = (const float*)d_in[5];
    const float* val_w   = (const float*)d_in[6];
    const float* val_b   = (const float*)d_in[7];
    const float* up_w    = (const float*)d_in[8];
    const float* up_b    = (const float*)d_in[9];
    float* out = (float*)d_out;

    __half *khbuf, *qphbuf, *vhbuf, *ohbuf, *xhbuf, *qhbuf, *whbuf;
    float *spbuf, *pbuf;
    cudaGetSymbolAddress((void**)&khbuf, g_kh);
    cudaGetSymbolAddress((void**)&qphbuf, g_qph);
    cudaGetSymbolAddress((void**)&vhbuf, g_vh);
    cudaGetSymbolAddress((void**)&ohbuf, g_oh);
    cudaGetSymbolAddress((void**)&xhbuf, g_xh);
    cudaGetSymbolAddress((void**)&qhbuf, g_qh);
    cudaGetSymbolAddress((void**)&whbuf, g_wh);
    cudaGetSymbolAddress((void**)&spbuf, g_spart);
    cudaGetSymbolAddress((void**)&pbuf, g_p);

    cudaFuncSetAttribute(proj3_kernel,
                         cudaFuncAttributeMaxDynamicSharedMemorySize, GEMM_SMEM_BYTES);
    cudaFuncSetAttribute(up_kernel,
                         cudaFuncAttributeMaxDynamicSharedMemorySize, GEMM_SMEM_BYTES);

    // 1) fp32 -> fp16 conversions (single fused launch)
    convert_all_kernel<<<2048, 256>>>(x, query, xhbuf, qhbuf,
                                      key_w, query_w, val_w, up_w, whbuf);

    // 2) projections (fused, fp16 out)
    ProjArgs pa;
    pa.X[0] = xhbuf;    pa.X[1] = qhbuf;      pa.X[2] = xhbuf;
    pa.Y[0] = khbuf;    pa.Y[1] = qphbuf;     pa.Y[2] = vhbuf;
    pa.bias[0] = key_b; pa.bias[1] = query_b; pa.bias[2] = val_b;

    const dim3 gblk(GTHREADS);
    const dim3 grid_proj((NSP + 127) / 128, COUT / 128, 3 * B_);   // (13, 4, 96)
    const dim3 grid_up((NSP + 127) / 128, CIN / 128, B_);          // (13, 8, 32)

    proj3_kernel<<<grid_proj, gblk, GEMM_SMEM_BYTES>>>(pa, whbuf);

    // 3) attention: S partials (tensor cores) -> softmax -> O
    attn_s_kernel<<<dim3(B_ * NHEAD, NCHUNK_S), 128>>>(khbuf, qphbuf, spbuf);
    attn_softmax_kernel<<<B_ * NHEAD, 256>>>(spbuf, pbuf);
    attn_o_kernel<<<dim3(B_ * NHEAD, NCHUNK_O), 256>>>(pbuf, vhbuf, ohbuf);

    // 4) up projection (fp32 out)
    up_kernel<<<grid_up, gblk, GEMM_SMEM_BYTES>>>(whbuf, ohbuf, up_b, out);
}

// round 17
// speedup vs baseline: 1.0521x; 1.0018x over previous
#include <cuda_runtime.h>
#include <cuda_fp16.h>
#include <cstdint>

// Problem constants
#define B_   32
#define CIN  1024
#define COUT 512
#define NSP  1568          // T*H*W = 8*14*14
#define NHEAD 8
#define DK   64
#define NCHUNK_S 7         // attn_s: 224-row chunks
#define CHUNK_S  224
#define NCHUNK_O 25        // attn_o: 64-row chunks (last = 32)

// Scratch buffers (device globals: allocation-free contract)
__device__ __half g_kh[(size_t)B_ * COUT * NSP];
__device__ __half g_qph[(size_t)B_ * COUT * NSP];
__device__ __half g_vh[(size_t)B_ * COUT * NSP];
__device__ __half g_oh[(size_t)B_ * COUT * NSP];
__device__ __half g_xh[(size_t)B_ * CIN * NSP];
__device__ __half g_qh[(size_t)B_ * CIN * NSP];
__device__ __half g_wh[4 * 512 * 1024];          // key_w, query_w, val_w, up_w
__device__ float  g_spart[(size_t)B_ * NHEAD * NCHUNK_S * DK * DK];
__device__ float  g_p[(size_t)B_ * NHEAD * DK * DK];

// ---------------------------------------------------------------------------
// PTX helpers
// ---------------------------------------------------------------------------
__device__ __forceinline__ uint32_t smem_u32(const void* p) {
    uint32_t a;
    asm("{ .reg .u64 t; cvta.to.shared.u64 t, %1; cvt.u32.u64 %0, t; }"
        : "=r"(a) : "l"(p));
    return a;
}

__device__ __forceinline__ void cp16(uint32_t dst, const void* src, uint32_t srcsize) {
    asm volatile("cp.async.cg.shared.global [%0], [%1], 16, %2;"
                 :: "r"(dst), "l"(src), "r"(srcsize) : "memory");
}
#define CP_COMMIT() asm volatile("cp.async.commit_group;" ::: "memory")
#define CP_WAIT1()  asm volatile("cp.async.wait_group 1;" ::: "memory")

__device__ __forceinline__ void ldsm4(uint32_t* r, uint32_t addr) {
    asm volatile("ldmatrix.sync.aligned.m8n8.x4.shared.b16 {%0,%1,%2,%3}, [%4];"
                 : "=r"(r[0]), "=r"(r[1]), "=r"(r[2]), "=r"(r[3]) : "r"(addr));
}
__device__ __forceinline__ void ldsm4t(uint32_t* r, uint32_t addr) {
    asm volatile("ldmatrix.sync.aligned.m8n8.x4.trans.shared.b16 {%0,%1,%2,%3}, [%4];"
                 : "=r"(r[0]), "=r"(r[1]), "=r"(r[2]), "=r"(r[3]) : "r"(addr));
}

__device__ __forceinline__ void mma16(float* d, const uint32_t* a, const uint32_t* b) {
    asm volatile(
        "mma.sync.aligned.m16n8k16.row.col.f32.f16.f16.f32 "
        "{%0,%1,%2,%3},{%4,%5,%6,%7},{%8,%9},{%0,%1,%2,%3};"
        : "+f"(d[0]), "+f"(d[1]), "+f"(d[2]), "+f"(d[3])
        : "r"(a[0]), "r"(a[1]), "r"(a[2]), "r"(a[3]), "r"(b[0]), "r"(b[1]));
}

// ---------------------------------------------------------------------------
// FP16 GEMM: Y[m,n] = sum_k A[m,k]*B[k,n] + bias[m]     (R13 config, frozen)
// BM=BN=128, BK=64, 128 threads (4 warps 2m x 2n), warp tile 64x64.
// 3-stage cp.async pipeline; ldmatrix (A: 144B rows, B: 272B rows, both
// conflict-free). 2 CTAs/SM. M%128==0, K%64==0.
// ---------------------------------------------------------------------------
#define A_ROWB   144
#define B_ROWB   272
#define A_BYTES  (128 * A_ROWB)            // 18432
#define B_BYTES  (64 * B_ROWB)             // 17408
#define STAGE_B  (A_BYTES + B_BYTES)       // 35840
#define GEMM_SMEM_BYTES (3 * STAGE_B)      // 107520
#define GTHREADS 128

__device__ __forceinline__ void gemm_issue(
    const __half* __restrict__ A, const __half* __restrict__ B,
    int K, int N, int m0, int n0, int kt, uint32_t sbase, int tid)
{
    const uint32_t st = sbase + (kt % 3) * STAGE_B;
#pragma unroll
    for (int i = 0; i < 8; i++) {
        const int id = tid + GTHREADS * i;
        const int r = id >> 3, c = id & 7;
        cp16(st + r * A_ROWB + c * 16,
             A + (size_t)(m0 + r) * K + kt * 64 + c * 8, 16);
    }
#pragma unroll
    for (int i = 0; i < 8; i++) {
        const int id = tid + GTHREADS * i;
        const int k = id >> 4, c = id & 15;
        const int n = n0 + c * 8;
        cp16(st + A_BYTES + k * B_ROWB + c * 16,
             B + (size_t)(kt * 64 + k) * N + n, (n < N) ? 16u : 0u);
    }
}

template <bool HALF_OUT, typename OutT>
__device__ __forceinline__ void gemm_body(
    const __half* __restrict__ A, const __half* __restrict__ B,
    const float* __restrict__ bias, OutT* __restrict__ Y,
    int M, int N, int K, int m0, int n0, uint8_t* smem)
{
    const int tid  = threadIdx.x;
    const int lane = tid & 31;
    const int w    = tid >> 5;          // 0..3
    const int g    = lane >> 2;
    const int c    = lane & 3;
    const int wm   = (w & 1) << 6;      // 0/64
    const int wn   = (w >> 1) << 6;     // 0/64

    const uint32_t sbase = smem_u32(smem);
    const int KT = K >> 6;

    float acc[4][8][4];
#pragma unroll
    for (int mt = 0; mt < 4; mt++)
#pragma unroll
        for (int nt = 0; nt < 8; nt++)
#pragma unroll
            for (int r = 0; r < 4; r++) acc[mt][nt][r] = 0.f;

    const uint32_t a_addr = (uint32_t)((wm + (lane & 15)) * A_ROWB + (lane >> 4) * 16);
    const uint32_t b_addr = (uint32_t)(A_BYTES + (lane & 15) * B_ROWB
                                       + (wn + (lane >> 4) * 8) * 2);

    // prologue: 2 stages in flight
    gemm_issue(A, B, K, N, m0, n0, 0, sbase, tid); CP_COMMIT();
    if (KT > 1) gemm_issue(A, B, K, N, m0, n0, 1, sbase, tid);
    CP_COMMIT();

    for (int kt = 0; kt < KT; kt++) {
        CP_WAIT1();                 // stage kt resident
        __syncthreads();
        if (kt + 2 < KT) gemm_issue(A, B, K, N, m0, n0, kt + 2, sbase, tid);
        CP_COMMIT();

        const uint32_t st = sbase + (kt % 3) * STAGE_B;
#pragma unroll
        for (int ks = 0; ks < 4; ks++) {
            uint32_t af[4][4];
#pragma unroll
            for (int mt = 0; mt < 4; mt++)
                ldsm4(af[mt], st + a_addr + mt * 16 * A_ROWB + ks * 32);
            uint32_t bf[8][2];
#pragma unroll
            for (int p = 0; p < 4; p++) {
                uint32_t t[4];
                ldsm4t(t, st + b_addr + ks * 16 * B_ROWB + p * 32);
                bf[2 * p][0] = t[0]; bf[2 * p][1] = t[1];
                bf[2 * p + 1][0] = t[2]; bf[2 * p + 1][1] = t[3];
            }
#pragma unroll
            for (int mt = 0; mt < 4; mt++)
#pragma unroll
                for (int nt = 0; nt < 8; nt++)
                    mma16(acc[mt][nt], af[mt], bf[nt]);
        }
    }

    // ---- epilogue: bias + guarded stores ----
#pragma unroll
    for (int mt = 0; mt < 4; mt++) {
        const int mrow = m0 + wm + mt * 16 + g;
        const float bb0 = bias[mrow];
        const float bb1 = bias[mrow + 8];
#pragma unroll
        for (int nt = 0; nt < 8; nt++) {
            const int n = n0 + wn + nt * 8 + 2 * c;
            if (n < N) {
                if (HALF_OUT) {
                    __half2 h0 = __floats2half2_rn(acc[mt][nt][0] + bb0,
                                                   acc[mt][nt][1] + bb0);
                    __half2 h1 = __floats2half2_rn(acc[mt][nt][2] + bb1,
                                                   acc[mt][nt][3] + bb1);
                    *(__half2*)((__half*)Y + (size_t)mrow * N + n)       = h0;
                    *(__half2*)((__half*)Y + (size_t)(mrow + 8) * N + n) = h1;
                } else {
                    float2 o0, o1;
                    o0.x = acc[mt][nt][0] + bb0; o0.y = acc[mt][nt][1] + bb0;
                    o1.x = acc[mt][nt][2] + bb1; o1.y = acc[mt][nt][3] + bb1;
                    *(float2*)((float*)Y + (size_t)mrow * N + n)       = o0;
                    *(float2*)((float*)Y + (size_t)(mrow + 8) * N + n) = o1;
                }
            }
        }
    }
}

// ---------------------------------------------------------------------------
// Fused conversion kernel: inputs (x, query) + 4 weight matrices
// ---------------------------------------------------------------------------
__global__ void __launch_bounds__(256)
convert_all_kernel(const float* __restrict__ x, const float* __restrict__ q,
                   __half* __restrict__ xh, __half* __restrict__ qh,
                   const float* __restrict__ w0, const float* __restrict__ w1,
                   const float* __restrict__ w2, const float* __restrict__ w3,
                   __half* __restrict__ wdst)
{
    const size_t n4in = (size_t)B_ * CIN * NSP / 4;       // float4s per input
    const int    seg  = 512 * 1024 / 4;                   // float4s per weight
    const size_t total = 2 * n4in + 4 * (size_t)seg;
    const size_t stride = (size_t)gridDim.x * blockDim.x;
    for (size_t i = (size_t)blockIdx.x * blockDim.x + threadIdx.x; i < total; i += stride) {
        const float* src; __half* dst; size_t j;
        if (i < n4in)            { src = x; dst = xh; j = i; }
        else if (i < 2 * n4in)   { src = q; dst = qh; j = i - n4in; }
        else {
            size_t wi = i - 2 * n4in;
            const int which = (int)(wi / seg);
            j = wi % seg;
            src = (which == 0) ? w0 : (which == 1) ? w1 : (which == 2) ? w2 : w3;
            dst = wdst + (size_t)which * 512 * 1024;
        }
        float4 v = ((const float4*)src)[j];
        ((__half2*)dst)[2 * j]     = __floats2half2_rn(v.x, v.y);
        ((__half2*)dst)[2 * j + 1] = __floats2half2_rn(v.z, v.w);
    }
}

// ---------------------------------------------------------------------------
// GEMM launch wrappers
// ---------------------------------------------------------------------------
struct ProjArgs {
    const __half* X[3];
    __half*       Y[3];
    const float*  bias[3];
};

__global__ void __launch_bounds__(GTHREADS, 2)
proj3_kernel(ProjArgs pa, const __half* __restrict__ Wh)
{
    extern __shared__ uint8_t smem[];
    const int which = blockIdx.z % 3;
    const int b     = blockIdx.z / 3;
    gemm_body<true>(Wh + (size_t)which * 512 * 1024,
                    pa.X[which] + (size_t)b * CIN * NSP,
                    pa.bias[which],
                    pa.Y[which] + (size_t)b * COUT * NSP,
                    COUT, NSP, CIN, blockIdx.y * 128, blockIdx.x * 128, smem);
}

__global__ void __launch_bounds__(GTHREADS, 2)
up_kernel(const __half* __restrict__ Wh, const __half* __restrict__ X,
          const float* __restrict__ bias, float* __restrict__ Y)
{
    extern __shared__ uint8_t smem[];
    const int b = blockIdx.z;
    gemm_body<false>(Wh + (size_t)3 * 512 * 1024,
                     X + (size_t)b * COUT * NSP, bias, Y + (size_t)b * CIN * NSP,
                     CIN, NSP, COUT, blockIdx.y * 128, blockIdx.x * 128, smem);
}

// ---------------------------------------------------------------------------
// Attention — S via tensor cores (double-buffered tiles, 7 chunks),
// parallel softmax (7 partials), O SIMT (double-buffered V, 25 chunks).
// K/Q/V fp16, layout [n][512], head h at column h*64.
// ---------------------------------------------------------------------------
#define KST 72    // halves; 144B rows -> ldmatrix conflict-free

__global__ void __launch_bounds__(128)
attn_s_kernel(const __half* __restrict__ Kp, const __half* __restrict__ Qp,
              float* __restrict__ Sp)
{
    const int bh = blockIdx.x;
    const int ch = blockIdx.y;
    const int b = bh >> 3;
    const int h = bh & 7;
    const size_t base = (size_t)b * (COUT * NSP);
    const __half* Kb = Kp + base + h * DK;
    const __half* Qb = Qp + base + h * DK;

    __shared__ __half Ksm[2][32 * KST];
    __shared__ __half Qsm[2][32 * KST];
    const uint32_t ksb = smem_u32(Ksm);
    const uint32_t qsb = smem_u32(Qsm);

    const int tid  = threadIdx.x;
    const int lane = tid & 31;
    const int w    = tid >> 5;
    const int wm   = (w & 1) << 5;
    const int wn   = (w >> 1) << 5;

    float acc[2][4][4];
#pragma unroll
    for (int mt = 0; mt < 2; mt++)
#pragma unroll
        for (int nt = 0; nt < 4; nt++)
#pragma unroll
            for (int r = 0; r < 4; r++) acc[mt][nt][r] = 0.f;

    const int r  = tid >> 3;             // 0..15
    const int c8 = (tid & 7) << 3;       // 0..56

    const int n0 = ch * CHUNK_S;
    const int n1 = n0 + CHUNK_S;

    uint4 kr[2], qr[2];
    // fetch tile n0
#pragma unroll
    for (int u = 0; u < 2; u++) {
        const size_t gg = (size_t)(n0 + r + u * 16) * COUT + c8;
        kr[u] = *(const uint4*)&Kb[gg];
        qr[u] = *(const uint4*)&Qb[gg];
    }
    // stage into buf 0
#pragma unroll
    for (int u = 0; u < 2; u++) {
        *(uint4*)&Ksm[0][(r + u * 16) * KST + c8] = kr[u];
        *(uint4*)&Qsm[0][(r + u * 16) * KST + c8] = qr[u];
    }
    __syncthreads();

    int it = 0;
    for (int nb = n0; nb < n1; nb += 32, it++) {
        const int cur = it & 1;
        const bool more = (nb + 32 < n1);
        if (more) {
#pragma unroll
            for (int u = 0; u < 2; u++) {
                const size_t gg = (size_t)(nb + 32 + r + u * 16) * COUT + c8;
                kr[u] = *(const uint4*)&Kb[gg];
                qr[u] = *(const uint4*)&Qb[gg];
            }
        }

        const uint32_t kb = ksb + (uint32_t)(cur * 32 * KST * 2);
        const uint32_t qb = qsb + (uint32_t)(cur * 32 * KST * 2);
#pragma unroll
        for (int s = 0; s < 2; s++) {
            const uint32_t krow = (uint32_t)((s * 16 + (lane & 15)) * KST * 2);
            const uint32_t cblk = (uint32_t)((lane >> 4) * 8 * 2);
            uint32_t t[4];
            uint32_t af[2][4];
#pragma unroll
            for (int mt = 0; mt < 2; mt++) {
                ldsm4t(t, kb + krow + (uint32_t)((wm + mt * 16) * 2) + cblk);
                af[mt][0] = t[0]; af[mt][1] = t[2];
                af[mt][2] = t[1]; af[mt][3] = t[3];
            }
            uint32_t bf[4][2];
#pragma unroll
            for (int p = 0; p < 2; p++) {
                ldsm4t(t, qb + krow + (uint32_t)((wn + p * 16) * 2) + cblk);
                bf[2 * p][0] = t[0]; bf[2 * p][1] = t[1];
                bf[2 * p + 1][0] = t[2]; bf[2 * p + 1][1] = t[3];
            }
#pragma unroll
            for (int mt = 0; mt < 2; mt++)
#pragma unroll
                for (int nt = 0; nt < 4; nt++)
                    mma16(acc[mt][nt], af[mt], bf[nt]);
        }

        if (more) {
            const int nxt = cur ^ 1;
#pragma unroll
            for (int u = 0; u < 2; u++) {
                *(uint4*)&Ksm[nxt][(r + u * 16) * KST + c8] = kr[u];
                *(uint4*)&Qsm[nxt][(r + u * 16) * KST + c8] = qr[u];
            }
        }
        __syncthreads();
    }

    float* out = Sp + ((size_t)bh * NCHUNK_S + ch) * (DK * DK);
    const int g = lane >> 2, cc = lane & 3;
#pragma unroll
    for (int mt = 0; mt < 2; mt++) {
        const int i0 = wm + mt * 16 + g;
#pragma unroll
        for (int nt = 0; nt < 4; nt++) {
            const int j = wn + nt * 8 + 2 * cc;
            float2 d0, d1;
            d0.x = acc[mt][nt][0]; d0.y = acc[mt][nt][1];
            d1.x = acc[mt][nt][2]; d1.y = acc[mt][nt][3];
            *(float2*)&out[i0 * DK + j]       = d0;
            *(float2*)&out[(i0 + 8) * DK + j] = d1;
        }
    }
}

// Softmax: grid 256, block 256. 4 threads per row; 16 cols each.
__global__ void __launch_bounds__(256)
attn_softmax_kernel(const float* __restrict__ Sp, float* __restrict__ P)
{
    const int bh = blockIdx.x;
    const int i  = threadIdx.x >> 2;
    const int q  = threadIdx.x & 3;

    const float* sp = Sp + (size_t)bh * NCHUNK_S * DK * DK + i * DK + q * 16;
    float4 s[4];
#pragma unroll
    for (int v = 0; v < 4; v++) s[v] = ((const float4*)sp)[v];
    for (int c = 1; c < NCHUNK_S; c++) {
        const float4* qq = (const float4*)(sp + c * DK * DK);
#pragma unroll
        for (int v = 0; v < 4; v++) {
            float4 t = qq[v];
            s[v].x += t.x; s[v].y += t.y; s[v].z += t.z; s[v].w += t.w;
        }
    }
    float mx = -1e30f;
#pragma unroll
    for (int v = 0; v < 4; v++) {
        s[v].x *= 0.125f; s[v].y *= 0.125f; s[v].z *= 0.125f; s[v].w *= 0.125f;
        mx = fmaxf(mx, fmaxf(fmaxf(s[v].x, s[v].y), fmaxf(s[v].z, s[v].w)));
    }
    mx = fmaxf(mx, __shfl_xor_sync(0xffffffffu, mx, 1));
    mx = fmaxf(mx, __shfl_xor_sync(0xffffffffu, mx, 2));

    float sum = 0.f;
#pragma unroll
    for (int v = 0; v < 4; v++) {
        s[v].x = expf(s[v].x - mx); s[v].y = expf(s[v].y - mx);
        s[v].z = expf(s[v].z - mx); s[v].w = expf(s[v].w - mx);
        sum += s[v].x + s[v].y + s[v].z + s[v].w;
    }
    sum += __shfl_xor_sync(0xffffffffu, sum, 1);
    sum += __shfl_xor_sync(0xffffffffu, sum, 2);
    const float inv = 1.0f / sum;

    float* out = P + (size_t)bh * DK * DK + i * DK + q * 16;
#pragma unroll
    for (int v = 0; v < 4; v++) {
        float4 o;
        o.x = s[v].x * inv; o.y = s[v].y * inv;
        o.z = s[v].z * inv; o.w = s[v].w * inv;
        ((float4*)out)[v] = o;
    }
}

#define PST 68    // floats; 272B rows, float4-aligned
__global__ void __launch_bounds__(256)
attn_o_kernel(const float* __restrict__ P, const __half* __restrict__ Vp,
              __half* __restrict__ Op)
{
    const int bh = blockIdx.x;
    const int ch = blockIdx.y;
    const int b = bh >> 3;
    const int h = bh & 7;
    const size_t base = (size_t)b * (COUT * NSP);
    const __half* Vb = Vp + base + h * DK;
    __half*       Ob = Op + base;

    __shared__ float Ps[64 * PST];
    __shared__ float Vs[2][32 * PST];

    const int tid = threadIdx.x;
    const int tx = tid & 15;
    const int ty = tid >> 4;

    const int n0   = ch * 64;
    const int nend = (n0 + 64 < NSP) ? (n0 + 64) : NSP;

    const int r  = tid >> 3;          // 0..31
    const int c8 = (tid & 7) << 3;    // 0..56

    // fetch tile n0 (registers) while loading P
    uint4 vr = *(const uint4*)&Vb[(size_t)(n0 + r) * COUT + c8];

    {
        const float* p = P + (size_t)bh * DK * DK;
#pragma unroll
        for (int u = 0; u < 4; u++) {
            const int idx = tid + u * 256;
            const int row = idx >> 4;
            const int c4  = (idx & 15) << 2;
            *(float4*)&Ps[row * PST + c4] = *(const float4*)&p[row * DK + c4];
        }
    }
    // stage tile n0 into buf 0
    {
        const __half2* h2 = (const __half2*)&vr;
#pragma unroll
        for (int q = 0; q < 4; q++) {
            float2 f = __half22float2(h2[q]);
            Vs[0][r * PST + c8 + 2 * q]     = f.x;
            Vs[0][r * PST + c8 + 2 * q + 1] = f.y;
        }
    }
    __syncthreads();

    int it = 0;
    for (int nb = n0; nb < nend; nb += 32, it++) {
        const int cur = it & 1;
        const bool more = (nb + 32 < nend);
        if (more)
            vr = *(const uint4*)&Vb[(size_t)(nb + 32 + r) * COUT + c8];

        float o[4][2];
#pragma unroll
        for (int i = 0; i < 4; i++) { o[i][0] = 0.f; o[i][1] = 0.f; }
#pragma unroll
        for (int j = 0; j < 64; j += 4) {
            const float4 v0 = *(const float4*)&Vs[cur][tx * PST + j];
            const float4 v1 = *(const float4*)&Vs[cur][(16 + tx) * PST + j];
#pragma unroll
            for (int i = 0; i < 4; i++) {
                const float4 p = *(const float4*)&Ps[(ty * 4 + i) * PST + j];
                o[i][0] += p.x * v0.x + p.y * v0.y + p.z * v0.z + p.w * v0.w;
                o[i][1] += p.x * v1.x + p.y * v1.y + p.z * v1.z + p.w * v1.w;
            }
        }
#pragma unroll
        for (int i = 0; i < 4; i++) {
            const int o2 = (ty * 4 + i) * NHEAD + h;
            Ob[(size_t)o2 * NSP + nb + tx]      = __float2half(o[i][0]);
            Ob[(size_t)o2 * NSP + nb + 16 + tx] = __float2half(o[i][1]);
        }

        if (more) {
            const int nxt = cur ^ 1;
            const __half2* h2 = (const __half2*)&vr;
#pragma unroll
            for (int q = 0; q < 4; q++) {
                float2 f = __half22float2(h2[q]);
                Vs[nxt][r * PST + c8 + 2 * q]     = f.x;
                Vs[nxt][r * PST + c8 + 2 * q + 1] = f.y;
            }
        }
        __syncthreads();
    }
}

// ---------------------------------------------------------------------------
// Launch
// ---------------------------------------------------------------------------
extern "C" void kernel_launch(void* const* d_in, const int* in_sizes, int n_in,
                              void* d_out, int out_size)
{
    const float* x       = (const float*)d_in[0];
    const float* query   = (const float*)d_in[1];
    const float* key_w   = (const float*)d_in[2];
    const float* key_b   = (const float*)d_in[3];
    const float* query_w = (const float*)d_in[4];
    const float* query_b = (const float*)d_in[5];
    const float* val_w   = (const float*)d_in[6];
    const float* val_b   = (const float*)d_in[7];
    const float* up_w    = (const float*)d_in[8];
    const float* up_b    = (const float*)d_in[9];
    float* out = (float*)d_out;

    __half *khbuf, *qphbuf, *vhbuf, *ohbuf, *xhbuf, *qhbuf, *whbuf;
    float *spbuf, *pbuf;
    cudaGetSymbolAddress((void**)&khbuf, g_kh);
    cudaGetSymbolAddress((void**)&qphbuf, g_qph);
    cudaGetSymbolAddress((void**)&vhbuf, g_vh);
    cudaGetSymbolAddress((void**)&ohbuf, g_oh);
    cudaGetSymbolAddress((void**)&xhbuf, g_xh);
    cudaGetSymbolAddress((void**)&qhbuf, g_qh);
    cudaGetSymbolAddress((void**)&whbuf, g_wh);
    cudaGetSymbolAddress((void**)&spbuf, g_spart);
    cudaGetSymbolAddress((void**)&pbuf, g_p);

    cudaFuncSetAttribute(proj3_kernel,
                         cudaFuncAttributeMaxDynamicSharedMemorySize, GEMM_SMEM_BYTES);
    cudaFuncSetAttribute(up_kernel,
                         cudaFuncAttributeMaxDynamicSharedMemorySize, GEMM_SMEM_BYTES);

    // 1) fp32 -> fp16 conversions (single fused launch)
    convert_all_kernel<<<2048, 256>>>(x, query, xhbuf, qhbuf,
                                      key_w, query_w, val_w, up_w, whbuf);

    // 2) projections (fused, fp16 out)
    ProjArgs pa;
    pa.X[0] = xhbuf;    pa.X[1] = qhbuf;      pa.X[2] = xhbuf;
    pa.Y[0] = khbuf;    pa.Y[1] = qphbuf;     pa.Y[2] = vhbuf;
    pa.bias[0] = key_b; pa.bias[1] = query_b; pa.bias[2] = val_b;

    const dim3 gblk(GTHREADS);
    const dim3 grid_proj((NSP + 127) / 128, COUT / 128, 3 * B_);   // (13, 4, 96)
    const dim3 grid_up((NSP + 127) / 128, CIN / 128, B_);          // (13, 8, 32)

    proj3_kernel<<<grid_proj, gblk, GEMM_SMEM_BYTES>>>(pa, whbuf);

    // 3) attention: S partials (tensor cores) -> softmax -> O
    attn_s_kernel<<<dim3(B_ * NHEAD, NCHUNK_S), 128>>>(khbuf, qphbuf, spbuf);
    attn_softmax_kernel<<<B_ * NHEAD, 256>>>(spbuf, pbuf);
    attn_o_kernel<<<dim3(B_ * NHEAD, NCHUNK_O), 256>>>(pbuf, vhbuf, ohbuf);

    // 4) up projection (fp32 out)
    up_kernel<<<grid_up, gblk, GEMM_SMEM_BYTES>>>(whbuf, ohbuf, up_b, out);
}